// round 12
// baseline (speedup 1.0000x reference)
#include <cuda_runtime.h>
#include <cuda_bf16.h>
#include <cstdint>

// B=1024, T=64, E=H=1024, 4H=4096, NCLS=2, VOCAB=50000
// INT8 IMMA (m16n8k32.s8) fixed-point-split engine.
//   x ~= s*(q1*256 + q0),  gates = sA*sB*(65536*T11 + 256*(T10+T01))
// 512 threads / 16 warps, warp tile 32x32, CTA tile 128x128, K-chunk 128,
// 3-stage cp.async pipeline (one __syncthreads per chunk, prefetch issued
// before the MMA block), ldmatrix loads, dependency-spaced MMA ordering,
// fused LSTM cell + classifier epilogue.

#define CTRL  1024
#define PITCH 144
#define ABUF  18432                    // 128 rows * 144
#define STAGE 73728                    // A1 | A0 | B1 | B0, 18432 each
#define NSTAGE 3
#define SMEM_BYTES (CTRL + NSTAGE * STAGE)  // 222208
#define QMAXF 32512.0f

// ------------------------- static device scratch -------------------------
__device__ float d_Xg[268435456];      // pre-gates (+bias), fragment order
__device__ float d_Cfrag[1048576];     // cell state, fragment order
__device__ __align__(256) signed char d_hq1[2][1048576];
__device__ __align__(256) signed char d_hq0[2][1048576];
__device__ __align__(256) signed char d_Wihq1[4194304];
__device__ __align__(256) signed char d_Wihq0[4194304];
__device__ __align__(256) signed char d_Whhq1[4194304];
__device__ __align__(256) signed char d_Whhq0[4194304];
__device__ __align__(256) signed char d_embq1[51200000];
__device__ __align__(256) signed char d_embq0[51200000];
__device__ unsigned d_absmax[4];       // 0=Wih 1=Whh 2=emb 3=h0
__device__ float d_logits[131072];     // [T][B][2]

// ------------------------- helpers -------------------------
__device__ __forceinline__ uint32_t smem_u32(const void* p) {
    uint32_t a;
    asm("{ .reg .u64 t; cvta.to.shared.u64 t, %1; cvt.u32.u64 %0, t; }" : "=r"(a) : "l"(p));
    return a;
}

#define CP16(dst, src) \
    asm volatile("cp.async.cg.shared.global [%0], [%1], 16;" :: "r"(dst), "l"(src) : "memory")
#define CP_COMMIT() asm volatile("cp.async.commit_group;" ::: "memory")
#define CP_WAIT1()  asm volatile("cp.async.wait_group 1;" ::: "memory")

#define LDSM4(r0, r1, r2, r3, addr) \
    asm volatile("ldmatrix.sync.aligned.m8n8.x4.shared.b16 {%0,%1,%2,%3}, [%4];" \
        : "=r"(r0), "=r"(r1), "=r"(r2), "=r"(r3) : "r"(addr))

__device__ __forceinline__ void mma_s8(int* d, const uint32_t* a, const uint32_t* b) {
    asm volatile(
        "mma.sync.aligned.m16n8k32.row.col.s32.s8.s8.s32 "
        "{%0,%1,%2,%3}, {%4,%5,%6,%7}, {%8,%9}, {%0,%1,%2,%3};\n"
        : "+r"(d[0]), "+r"(d[1]), "+r"(d[2]), "+r"(d[3])
        : "r"(a[0]), "r"(a[1]), "r"(a[2]), "r"(a[3]), "r"(b[0]), "r"(b[1]));
}

// CTA-local col cl in [0,128) -> global n: cl = wn*32 + nf*8 + f, nf = gate
__device__ __forceinline__ int n_of(int cl, int hc0) {
    int wn_ = cl >> 5;
    int nf  = (cl >> 3) & 3;
    int f   = cl & 7;
    return nf * 1024 + hc0 + wn_ * 8 + f;
}

__device__ __forceinline__ void quant16(float v, float inv_s, signed char* a1, signed char* a0) {
    int q = __float2int_rn(v * inv_s);
    q = max(-32512, min(32512, q));
    int q1 = (q + 128) >> 8;
    *a1 = (signed char)q1;
    *a0 = (signed char)(q - (q1 << 8));
}
__device__ __forceinline__ void quant16x4(float4 v, float inv_s, char4* o1, char4* o0) {
    char4 c1, c0;
    quant16(v.x, inv_s, &c1.x, &c0.x);
    quant16(v.y, inv_s, &c1.y, &c0.y);
    quant16(v.z, inv_s, &c1.z, &c0.z);
    quant16(v.w, inv_s, &c1.w, &c0.w);
    *o1 = c1; *o0 = c0;
}

// one K=128 chunk (4x k32), 3-term split, warp tile 32x32, dependency-spaced order
__device__ __forceinline__ void gemm_chunk_i8(
    int acc1[2][4][4], int acc2[2][4][4],
    uint32_t aH, uint32_t aL, uint32_t bH, uint32_t bL)
{
#pragma unroll
    for (int ks = 0; ks < 4; ks++) {
        uint32_t off = ks * 32;
        uint32_t a1[2][4], a0[2][4], b1[8], b0[8];
        LDSM4(a1[0][0], a1[0][1], a1[0][2], a1[0][3], aH + off);
        LDSM4(a1[1][0], a1[1][1], a1[1][2], a1[1][3], aH + 2304 + off);
        LDSM4(a0[0][0], a0[0][1], a0[0][2], a0[0][3], aL + off);
        LDSM4(a0[1][0], a0[1][1], a0[1][2], a0[1][3], aL + 2304 + off);
        LDSM4(b1[0], b1[1], b1[2], b1[3], bH + off);
        LDSM4(b1[4], b1[5], b1[6], b1[7], bH + 2304 + off);
        LDSM4(b0[0], b0[1], b0[2], b0[3], bL + off);
        LDSM4(b0[4], b0[5], b0[6], b0[7], bL + 2304 + off);
        // 8x T11, then 8x T10, then 8x T01 -> same-acc distance = 8
#pragma unroll
        for (int mf = 0; mf < 2; mf++)
#pragma unroll
            for (int nf = 0; nf < 4; nf++)
                mma_s8(acc1[mf][nf], a1[mf], b1 + nf * 2);
#pragma unroll
        for (int mf = 0; mf < 2; mf++)
#pragma unroll
            for (int nf = 0; nf < 4; nf++)
                mma_s8(acc2[mf][nf], a1[mf], b0 + nf * 2);
#pragma unroll
        for (int mf = 0; mf < 2; mf++)
#pragma unroll
            for (int nf = 0; nf < 4; nf++)
                mma_s8(acc2[mf][nf], a0[mf], b1 + nf * 2);
    }
}

// ------------------------- absmax pre-pass -------------------------
__global__ void zero_absmax() {
    if (threadIdx.x < 4) d_absmax[threadIdx.x] = 0u;
}

__device__ __forceinline__ float amax4(float4 v) {
    return fmaxf(fmaxf(fabsf(v.x), fabsf(v.y)), fmaxf(fabsf(v.z), fabsf(v.w)));
}

__global__ void absmax_kernel(const float* __restrict__ Wih, const float* __restrict__ Whh,
                              const float* __restrict__ emb, const float* __restrict__ h0)
{
    long g = blockIdx.x * 256 + threadIdx.x;
    const long stride = 262144;
    float m0 = 0.f, m1 = 0.f, m2 = 0.f, m3 = 0.f;
    for (long i = g; i < 1048576L; i += stride) {
        m0 = fmaxf(m0, amax4(*(const float4*)&Wih[i * 4]));
        m1 = fmaxf(m1, amax4(*(const float4*)&Whh[i * 4]));
    }
    for (long i = g; i < 12800000L; i += stride)
        m2 = fmaxf(m2, amax4(*(const float4*)&emb[i * 4]));
    m3 = amax4(*(const float4*)&h0[g * 4]);
#pragma unroll
    for (int off = 16; off > 0; off >>= 1) {
        m0 = fmaxf(m0, __shfl_xor_sync(0xffffffffu, m0, off));
        m1 = fmaxf(m1, __shfl_xor_sync(0xffffffffu, m1, off));
        m2 = fmaxf(m2, __shfl_xor_sync(0xffffffffu, m2, off));
        m3 = fmaxf(m3, __shfl_xor_sync(0xffffffffu, m3, off));
    }
    if ((threadIdx.x & 31) == 0) {
        atomicMax(&d_absmax[0], __float_as_uint(m0));
        atomicMax(&d_absmax[1], __float_as_uint(m1));
        atomicMax(&d_absmax[2], __float_as_uint(m2));
        atomicMax(&d_absmax[3], __float_as_uint(m3));
    }
}

// ------------------------- init: quantize weights/emb/h0, layout c0 -------------------------
__global__ void init_quant(const float* __restrict__ Wih, const float* __restrict__ Whh,
                           const float* __restrict__ emb,
                           const float* __restrict__ h0,  const float* __restrict__ c0)
{
    int idx = blockIdx.x * 256 + threadIdx.x;
    float iWih = QMAXF / fmaxf(__uint_as_float(d_absmax[0]), 1e-20f);
    float iWhh = QMAXF / fmaxf(__uint_as_float(d_absmax[1]), 1e-20f);
    float iEmb = QMAXF / fmaxf(__uint_as_float(d_absmax[2]), 1e-20f);
    float iH0  = QMAXF / fmaxf(__uint_as_float(d_absmax[3]), 1e-20f);

    if (idx < 1048576) {
        quant16x4(*(const float4*)&Wih[idx * 4], iWih,
                  (char4*)&d_Wihq1[idx * 4], (char4*)&d_Wihq0[idx * 4]);
        quant16x4(*(const float4*)&Whh[idx * 4], iWhh,
                  (char4*)&d_Whhq1[idx * 4], (char4*)&d_Whhq0[idx * 4]);
    }
    for (long i = idx; i < 12800000L; i += 4194304L)
        quant16x4(*(const float4*)&emb[i * 4], iEmb,
                  (char4*)&d_embq1[i * 4], (char4*)&d_embq0[i * 4]);
    if (idx < 262144)
        quant16x4(*(const float4*)&h0[idx * 4], iH0,
                  (char4*)&d_hq1[0][idx * 4], (char4*)&d_hq0[0][idx * 4]);
    if (idx < 1048576) {
        // c0 -> fragment layout (16-warp geometry)
        int b = idx >> 10, hc = idx & 1023;
        int bm = b >> 7, rb = b & 127;
        int wm = rb >> 5, mf = (rb >> 4) & 1, rr = (rb >> 3) & 1, g = rb & 7;
        int bn = hc >> 5, hcl = hc & 31;
        int wn = hcl >> 3, tg = (hcl & 7) >> 1, e = hcl & 1;
        int warp = wn * 4 + wm, lane = g * 4 + tg, q = rr * 2 + e;
        int ci = (((bm * 32 + bn) * 16 + warp) * 2 + mf) * 128 + lane * 4 + q;
        d_Cfrag[ci] = c0[idx];
    }
    if (idx < 131072) d_logits[idx] = 0.0f;
}

// ------------------------- input GEMM: Xg = emb[x] @ W_ih^T + (b_ih + b_hh) -------------------------
__global__ void __launch_bounds__(512, 1) input_gemm(const int* __restrict__ x,
                                                     const float* __restrict__ b_ih,
                                                     const float* __restrict__ b_hh)
{
    extern __shared__ char smem[];
    uint32_t sb = smem_u32(smem);
    int tid = threadIdx.x;
    int bn = blockIdx.x, bm = blockIdx.y;
    int warp = tid >> 5, lane = tid & 31;
    int wm = warp & 3, wn = warp >> 2;
    int g = lane >> 2, tg = lane & 3;
    int hc0 = bn * 32;

    float sAB = (__uint_as_float(d_absmax[2]) / QMAXF) * (__uint_as_float(d_absmax[0]) / QMAXF);
    float sHIc = sAB * 65536.0f, sLOc = sAB * 256.0f;

    int* toks = (int*)(smem + 512);
    if (tid < 128) {
        int row = bm * 128 + tid;          // row = t*B + b
        toks[tid] = x[(row & 1023) * 64 + (row >> 10)];
    }
    __syncthreads();

    int r = tid >> 2, c = tid & 3;
    uint32_t offA = (uint32_t)(r * PITCH + c * 16);   // first 64B of row; +64 for second half
    size_t aoff = (size_t)toks[r] * 1024 + c * 16;
    size_t boff = (size_t)n_of(r, hc0) * 1024 + c * 16;

    uint32_t laneA = (uint32_t)((wm * 32 + (lane & 15)) * PITCH + (lane >> 4) * 16);
    uint32_t laneB = (uint32_t)((wn * 32 + ((lane >> 4) << 3) + (lane & 7)) * PITCH
                                + ((lane >> 3) & 1) * 16);

    int acc1[2][4][4], acc2[2][4][4];
#pragma unroll
    for (int i = 0; i < 2; i++)
#pragma unroll
        for (int j = 0; j < 4; j++)
#pragma unroll
            for (int q = 0; q < 4; q++) { acc1[i][j][q] = 0; acc2[i][j][q] = 0; }

    // prefetch chunks 0..1 into stages 0..1
#pragma unroll
    for (int p = 0; p < 2; p++) {
        uint32_t st = sb + CTRL + p * STAGE;
        int k0 = p * 128;
        CP16(st +            offA,      d_embq1 + aoff + k0);
        CP16(st +            offA + 64, d_embq1 + aoff + k0 + 64);
        CP16(st + ABUF +     offA,      d_embq0 + aoff + k0);
        CP16(st + ABUF +     offA + 64, d_embq0 + aoff + k0 + 64);
        CP16(st + 2 * ABUF + offA,      d_Wihq1 + boff + k0);
        CP16(st + 2 * ABUF + offA + 64, d_Wihq1 + boff + k0 + 64);
        CP16(st + 3 * ABUF + offA,      d_Wihq0 + boff + k0);
        CP16(st + 3 * ABUF + offA + 64, d_Wihq0 + boff + k0 + 64);
        CP_COMMIT();
    }

    for (int kt = 0; kt < 8; kt++) {
        CP_WAIT1();
        __syncthreads();
        // prefetch chunk kt+2 BEFORE the MMA block so DMA overlaps compute
        if (kt + 2 < 8) {
            int k0 = (kt + 2) * 128;
            uint32_t st = sb + CTRL + ((kt + 2) % 3) * STAGE;
            CP16(st +            offA,      d_embq1 + aoff + k0);
            CP16(st +            offA + 64, d_embq1 + aoff + k0 + 64);
            CP16(st + ABUF +     offA,      d_embq0 + aoff + k0);
            CP16(st + ABUF +     offA + 64, d_embq0 + aoff + k0 + 64);
            CP16(st + 2 * ABUF + offA,      d_Wihq1 + boff + k0);
            CP16(st + 2 * ABUF + offA + 64, d_Wihq1 + boff + k0 + 64);
            CP16(st + 3 * ABUF + offA,      d_Wihq0 + boff + k0);
            CP16(st + 3 * ABUF + offA + 64, d_Wihq0 + boff + k0 + 64);
        }
        CP_COMMIT();
        uint32_t s0 = sb + CTRL + (kt % 3) * STAGE;
        gemm_chunk_i8(acc1, acc2, s0 + laneA, s0 + ABUF + laneA,
                                  s0 + 2 * ABUF + laneB, s0 + 3 * ABUF + laneB);
    }

    // epilogue: combine terms, add biases, store in fragment order
#pragma unroll
    for (int mf = 0; mf < 2; mf++)
#pragma unroll
        for (int nf = 0; nf < 4; nf++) {
            int n0 = nf * 1024 + hc0 + wn * 8 + 2 * tg;
            float be0 = b_ih[n0] + b_hh[n0];
            float be1 = b_ih[n0 + 1] + b_hh[n0 + 1];
            size_t off = ((((size_t)bm * 32 + bn) * 16 + warp) * 8 + mf * 4 + nf) * 128 + lane * 4;
            float4 v;
            v.x = sHIc * (float)acc1[mf][nf][0] + sLOc * (float)acc2[mf][nf][0] + be0;
            v.y = sHIc * (float)acc1[mf][nf][1] + sLOc * (float)acc2[mf][nf][1] + be1;
            v.z = sHIc * (float)acc1[mf][nf][2] + sLOc * (float)acc2[mf][nf][2] + be0;
            v.w = sHIc * (float)acc1[mf][nf][3] + sLOc * (float)acc2[mf][nf][3] + be1;
            *(float4*)&d_Xg[off] = v;
        }
}

// ------------------------- one recurrent step -------------------------
__global__ void __launch_bounds__(512, 1) step_kernel(int t,
                                                      const float* __restrict__ Wout,
                                                      const float* __restrict__ b_out,
                                                      float* __restrict__ out)
{
    extern __shared__ char smem[];
    uint32_t sb = smem_u32(smem);
    int tid = threadIdx.x;
    int bn = blockIdx.x, bm = blockIdx.y;
    int warp = tid >> 5, lane = tid & 31;
    int wm = warp & 3, wn = warp >> 2;
    int g = lane >> 2, tg = lane & 3;
    int m0 = bm * 128, hc0 = bn * 32;

    if (t > 0 && bn == 0 && bm == 0) {
        int tb = (t - 1) << 11;
        for (int i = tid; i < 1024; i += 512) {
            float l0 = d_logits[tb + i * 2 + 0] + b_out[0];
            float l1 = d_logits[tb + i * 2 + 1] + b_out[1];
            float mx = fmaxf(l0, l1);
            float lse = mx + logf(expf(l0 - mx) + expf(l1 - mx));
            out[tb + i * 2 + 0] = l0 - lse;
            out[tb + i * 2 + 1] = l1 - lse;
        }
    }

    float sh  = (t == 0) ? (__uint_as_float(d_absmax[3]) / QMAXF) : (1.0f / QMAXF);
    float sAB = sh * (__uint_as_float(d_absmax[1]) / QMAXF);
    float sHIc = sAB * 65536.0f, sLOc = sAB * 256.0f;

    const signed char* hQ1 = d_hq1[t & 1];
    const signed char* hQ0 = d_hq0[t & 1];
    signed char* nQ1 = d_hq1[(t + 1) & 1];
    signed char* nQ0 = d_hq0[(t + 1) & 1];

    float* ws = (float*)smem;   // 64 floats: [cls][hcL 0..31]
    if (tid < 64) ws[tid] = Wout[(tid >> 5) * 1024 + hc0 + (tid & 31)];
    __syncthreads();

    int r = tid >> 2, c = tid & 3;
    uint32_t offA = (uint32_t)(r * PITCH + c * 16);
    size_t aoff = (size_t)(m0 + r) * 1024 + c * 16;
    size_t boff = (size_t)n_of(r, hc0) * 1024 + c * 16;

    uint32_t laneA = (uint32_t)((wm * 32 + (lane & 15)) * PITCH + (lane >> 4) * 16);
    uint32_t laneB = (uint32_t)((wn * 32 + ((lane >> 4) << 3) + (lane & 7)) * PITCH
                                + ((lane >> 3) & 1) * 16);

    int acc1[2][4][4], acc2[2][4][4];
#pragma unroll
    for (int i = 0; i < 2; i++)
#pragma unroll
        for (int j = 0; j < 4; j++)
#pragma unroll
            for (int q = 0; q < 4; q++) { acc1[i][j][q] = 0; acc2[i][j][q] = 0; }

    // prefetch chunks 0..1 into stages 0..1
#pragma unroll
    for (int p = 0; p < 2; p++) {
        uint32_t st = sb + CTRL + p * STAGE;
        int k0 = p * 128;
        CP16(st +            offA,      hQ1 + aoff + k0);
        CP16(st +            offA + 64, hQ1 + aoff + k0 + 64);
        CP16(st + ABUF +     offA,      hQ0 + aoff + k0);
        CP16(st + ABUF +     offA + 64, hQ0 + aoff + k0 + 64);
        CP16(st + 2 * ABUF + offA,      d_Whhq1 + boff + k0);
        CP16(st + 2 * ABUF + offA + 64, d_Whhq1 + boff + k0 + 64);
        CP16(st + 3 * ABUF + offA,      d_Whhq0 + boff + k0);
        CP16(st + 3 * ABUF + offA + 64, d_Whhq0 + boff + k0 + 64);
        CP_COMMIT();
    }

    for (int kt = 0; kt < 8; kt++) {
        CP_WAIT1();
        __syncthreads();
        if (kt + 2 < 8) {
            int k0 = (kt + 2) * 128;
            uint32_t st = sb + CTRL + ((kt + 2) % 3) * STAGE;
            CP16(st +            offA,      hQ1 + aoff + k0);
            CP16(st +            offA + 64, hQ1 + aoff + k0 + 64);
            CP16(st + ABUF +     offA,      hQ0 + aoff + k0);
            CP16(st + ABUF +     offA + 64, hQ0 + aoff + k0 + 64);
            CP16(st + 2 * ABUF + offA,      d_Whhq1 + boff + k0);
            CP16(st + 2 * ABUF + offA + 64, d_Whhq1 + boff + k0 + 64);
            CP16(st + 3 * ABUF + offA,      d_Whhq0 + boff + k0);
            CP16(st + 3 * ABUF + offA + 64, d_Whhq0 + boff + k0 + 64);
        }
        CP_COMMIT();
        uint32_t s0 = sb + CTRL + (kt % 3) * STAGE;
        gemm_chunk_i8(acc1, acc2, s0 + laneA, s0 + ABUF + laneA,
                                  s0 + 2 * ABUF + laneB, s0 + 3 * ABUF + laneB);
    }

    // ---------------- fused LSTM epilogue ----------------
    size_t xgbase = ((((size_t)(t * 8 + bm) * 32 + bn) * 16 + warp) * 8) * 128 + lane * 4;
    size_t cbase  = ((((size_t)bm * 32 + bn) * 16 + warp) * 2) * 128 + lane * 4;

    float lsum[2][2][2];
#pragma unroll
    for (int i = 0; i < 2; i++)
#pragma unroll
        for (int j = 0; j < 2; j++) { lsum[i][j][0] = 0.0f; lsum[i][j][1] = 0.0f; }

#pragma unroll
    for (int mf = 0; mf < 2; mf++) {
        float4 CPc = *(const float4*)&d_Cfrag[cbase + mf * 128];
        float cprev[4] = {CPc.x, CPc.y, CPc.z, CPc.w};
        float4 PI = *(const float4*)&d_Xg[xgbase + (size_t)(mf * 4 + 0) * 128];
        float4 PF = *(const float4*)&d_Xg[xgbase + (size_t)(mf * 4 + 1) * 128];
        float4 PG = *(const float4*)&d_Xg[xgbase + (size_t)(mf * 4 + 2) * 128];
        float4 PO = *(const float4*)&d_Xg[xgbase + (size_t)(mf * 4 + 3) * 128];
        float pri[4] = {PI.x, PI.y, PI.z, PI.w};
        float prf[4] = {PF.x, PF.y, PF.z, PF.w};
        float prg[4] = {PG.x, PG.y, PG.z, PG.w};
        float pro[4] = {PO.x, PO.y, PO.z, PO.w};
        float cnew[4];
#pragma unroll
        for (int q = 0; q < 4; q++) {
            int rr = q >> 1, e = q & 1;
            float I = sHIc * (float)acc1[mf][0][q] + sLOc * (float)acc2[mf][0][q] + pri[q];
            float F = sHIc * (float)acc1[mf][1][q] + sLOc * (float)acc2[mf][1][q] + prf[q];
            float G = sHIc * (float)acc1[mf][2][q] + sLOc * (float)acc2[mf][2][q] + prg[q];
            float O = sHIc * (float)acc1[mf][3][q] + sLOc * (float)acc2[mf][3][q] + pro[q];
            float si = 1.0f / (1.0f + expf(-I));
            float sf = 1.0f / (1.0f + expf(-F));
            float so = 1.0f / (1.0f + expf(-O));
            float c2 = sf * cprev[q] + si * tanhf(G);
            float h2 = so * tanhf(c2);
            cnew[q] = c2;
            int b  = m0 + wm * 32 + mf * 16 + rr * 8 + g;
            int hcL = wn * 8 + 2 * tg + e;
            int hc = hc0 + hcL;
            int qh = __float2int_rn(h2 * QMAXF);
            int qh1 = (qh + 128) >> 8;
            nQ1[b * 1024 + hc] = (signed char)qh1;
            nQ0[b * 1024 + hc] = (signed char)(qh - (qh1 << 8));
            lsum[mf][rr][0] += c2 * ws[hcL];
            lsum[mf][rr][1] += c2 * ws[32 + hcL];
        }
        *(float4*)&d_Cfrag[cbase + mf * 128] = make_float4(cnew[0], cnew[1], cnew[2], cnew[3]);
    }

#pragma unroll
    for (int mf = 0; mf < 2; mf++)
#pragma unroll
        for (int rr = 0; rr < 2; rr++)
#pragma unroll
            for (int cls = 0; cls < 2; cls++) {
                float v = lsum[mf][rr][cls];
                v += __shfl_xor_sync(0xffffffffu, v, 1);
                v += __shfl_xor_sync(0xffffffffu, v, 2);
                if (tg == 0) {
                    int b = m0 + wm * 32 + mf * 16 + rr * 8 + g;
                    atomicAdd(&d_logits[(t << 11) + b * 2 + cls], v);
                }
            }
}

// ------------------------- finalize t=63 + out_final -------------------------
__global__ void final_kernel(const float* __restrict__ b_out, float* __restrict__ out)
{
    int i = blockIdx.x * 256 + threadIdx.x;
    if (i < 1024) {
        int tb = 63 << 11;
        float l0 = d_logits[tb + i * 2 + 0] + b_out[0];
        float l1 = d_logits[tb + i * 2 + 1] + b_out[1];
        float mx = fmaxf(l0, l1);
        float lse = mx + logf(expf(l0 - mx) + expf(l1 - mx));
        out[tb + i * 2 + 0] = l0 - lse;
        out[tb + i * 2 + 1] = l1 - lse;
        out[131072 + i * 2 + 0] = l0;
        out[131072 + i * 2 + 1] = l1;
    }
}

// ------------------------- launch -------------------------
extern "C" void kernel_launch(void* const* d_in, const int* in_sizes, int n_in,
                              void* d_out, int out_size)
{
    (void)in_sizes; (void)n_in; (void)out_size;
    const int*   x    = (const int*)d_in[0];
    const float* emb  = (const float*)d_in[1];
    const float* Wih  = (const float*)d_in[2];
    const float* Whh  = (const float*)d_in[3];
    const float* bih  = (const float*)d_in[4];
    const float* bhh  = (const float*)d_in[5];
    const float* Wout = (const float*)d_in[6];
    const float* bout = (const float*)d_in[7];
    const float* h0   = (const float*)d_in[8];
    const float* c0   = (const float*)d_in[9];
    float* out = (float*)d_out;

    cudaFuncSetAttribute(input_gemm, cudaFuncAttributeMaxDynamicSharedMemorySize, SMEM_BYTES);
    cudaFuncSetAttribute(step_kernel, cudaFuncAttributeMaxDynamicSharedMemorySize, SMEM_BYTES);

    zero_absmax<<<1, 32>>>();
    absmax_kernel<<<1024, 256>>>(Wih, Whh, emb, h0);
    init_quant<<<16384, 256>>>(Wih, Whh, emb, h0, c0);
    input_gemm<<<dim3(32, 512), 512, SMEM_BYTES>>>(x, bih, bhh);
    for (int t = 0; t < 64; t++)
        step_kernel<<<dim3(32, 8), 512, SMEM_BYTES>>>(t, Wout, bout, out);
    final_kernel<<<4, 256>>>(bout, out);
}

// round 13
// speedup vs baseline: 1.0275x; 1.0275x over previous
#include <cuda_runtime.h>
#include <cuda_bf16.h>
#include <cstdint>

// B=1024, T=64, E=H=1024, 4H=4096, NCLS=2, VOCAB=50000
// INT8 IMMA (m16n8k32.s8) fixed-point-split engine.
//   x ~= s*(q1*256 + q0),  gates = sA*sB*(65536*T11 + 256*(T10+T01))
// 512 threads / 16 warps, warp tile 32x32, CTA tile 128x128 (K-chunk 64),
// 4-stage cp.async pipeline, ONE __syncthreads per chunk, prefetch hoisted
// BEFORE the MMA block, ldmatrix loads, dependency-spaced MMA ordering,
// fused LSTM cell + classifier epilogue.

#define CTRL  1024
#define STAGE 40960                    // A1 10240 | A0 10240 | B1 10240 | B0 10240
#define NSTAGE 4
#define SMEM_BYTES (CTRL + NSTAGE * STAGE)  // 164864
#define QMAXF 32512.0f

// ------------------------- static device scratch -------------------------
__device__ float d_Xg[268435456];      // pre-gates (+bias), fragment order
__device__ float d_Cfrag[1048576];     // cell state, fragment order
__device__ __align__(256) signed char d_hq1[2][1048576];
__device__ __align__(256) signed char d_hq0[2][1048576];
__device__ __align__(256) signed char d_Wihq1[4194304];
__device__ __align__(256) signed char d_Wihq0[4194304];
__device__ __align__(256) signed char d_Whhq1[4194304];
__device__ __align__(256) signed char d_Whhq0[4194304];
__device__ __align__(256) signed char d_embq1[51200000];
__device__ __align__(256) signed char d_embq0[51200000];
__device__ unsigned d_absmax[4];       // 0=Wih 1=Whh 2=emb 3=h0
__device__ float d_logits[131072];     // [T][B][2]

// ------------------------- helpers -------------------------
__device__ __forceinline__ uint32_t smem_u32(const void* p) {
    uint32_t a;
    asm("{ .reg .u64 t; cvta.to.shared.u64 t, %1; cvt.u32.u64 %0, t; }" : "=r"(a) : "l"(p));
    return a;
}

#define CP16(dst, src) \
    asm volatile("cp.async.cg.shared.global [%0], [%1], 16;" :: "r"(dst), "l"(src) : "memory")
#define CP_COMMIT() asm volatile("cp.async.commit_group;" ::: "memory")
#define CP_WAIT2()  asm volatile("cp.async.wait_group 2;" ::: "memory")

#define LDSM4(r0, r1, r2, r3, addr) \
    asm volatile("ldmatrix.sync.aligned.m8n8.x4.shared.b16 {%0,%1,%2,%3}, [%4];" \
        : "=r"(r0), "=r"(r1), "=r"(r2), "=r"(r3) : "r"(addr))

__device__ __forceinline__ void mma_s8(int* d, const uint32_t* a, const uint32_t* b) {
    asm volatile(
        "mma.sync.aligned.m16n8k32.row.col.s32.s8.s8.s32 "
        "{%0,%1,%2,%3}, {%4,%5,%6,%7}, {%8,%9}, {%0,%1,%2,%3};\n"
        : "+r"(d[0]), "+r"(d[1]), "+r"(d[2]), "+r"(d[3])
        : "r"(a[0]), "r"(a[1]), "r"(a[2]), "r"(a[3]), "r"(b[0]), "r"(b[1]));
}

// CTA-local col cl in [0,128) -> global n: cl = wn*32 + nf*8 + f, nf = gate
__device__ __forceinline__ int n_of(int cl, int hc0) {
    int wn_ = cl >> 5;
    int nf  = (cl >> 3) & 3;
    int f   = cl & 7;
    return nf * 1024 + hc0 + wn_ * 8 + f;
}

__device__ __forceinline__ void quant16(float v, float inv_s, signed char* a1, signed char* a0) {
    int q = __float2int_rn(v * inv_s);
    q = max(-32512, min(32512, q));
    int q1 = (q + 128) >> 8;
    *a1 = (signed char)q1;
    *a0 = (signed char)(q - (q1 << 8));
}
__device__ __forceinline__ void quant16x4(float4 v, float inv_s, char4* o1, char4* o0) {
    char4 c1, c0;
    quant16(v.x, inv_s, &c1.x, &c0.x);
    quant16(v.y, inv_s, &c1.y, &c0.y);
    quant16(v.z, inv_s, &c1.z, &c0.z);
    quant16(v.w, inv_s, &c1.w, &c0.w);
    *o1 = c1; *o0 = c0;
}

// one K=64 chunk (2x k32), 3-term split, warp tile 32x32, dependency-spaced order
__device__ __forceinline__ void gemm_chunk_i8(
    int acc1[2][4][4], int acc2[2][4][4],
    uint32_t aH, uint32_t aL, uint32_t bH, uint32_t bL)
{
#pragma unroll
    for (int ks = 0; ks < 2; ks++) {
        uint32_t off = ks * 32;
        uint32_t a1[2][4], a0[2][4], b1[8], b0[8];
        LDSM4(a1[0][0], a1[0][1], a1[0][2], a1[0][3], aH + off);
        LDSM4(a1[1][0], a1[1][1], a1[1][2], a1[1][3], aH + 1280 + off);
        LDSM4(a0[0][0], a0[0][1], a0[0][2], a0[0][3], aL + off);
        LDSM4(a0[1][0], a0[1][1], a0[1][2], a0[1][3], aL + 1280 + off);
        LDSM4(b1[0], b1[1], b1[2], b1[3], bH + off);
        LDSM4(b1[4], b1[5], b1[6], b1[7], bH + 1280 + off);
        LDSM4(b0[0], b0[1], b0[2], b0[3], bL + off);
        LDSM4(b0[4], b0[5], b0[6], b0[7], bL + 1280 + off);
        // 8x T11, then 8x T10, then 8x T01 -> same-acc distance = 8
#pragma unroll
        for (int mf = 0; mf < 2; mf++)
#pragma unroll
            for (int nf = 0; nf < 4; nf++)
                mma_s8(acc1[mf][nf], a1[mf], b1 + nf * 2);
#pragma unroll
        for (int mf = 0; mf < 2; mf++)
#pragma unroll
            for (int nf = 0; nf < 4; nf++)
                mma_s8(acc2[mf][nf], a1[mf], b0 + nf * 2);
#pragma unroll
        for (int mf = 0; mf < 2; mf++)
#pragma unroll
            for (int nf = 0; nf < 4; nf++)
                mma_s8(acc2[mf][nf], a0[mf], b1 + nf * 2);
    }
}

// ------------------------- absmax pre-pass -------------------------
__global__ void zero_absmax() {
    if (threadIdx.x < 4) d_absmax[threadIdx.x] = 0u;
}

__device__ __forceinline__ float amax4(float4 v) {
    return fmaxf(fmaxf(fabsf(v.x), fabsf(v.y)), fmaxf(fabsf(v.z), fabsf(v.w)));
}

__global__ void absmax_kernel(const float* __restrict__ Wih, const float* __restrict__ Whh,
                              const float* __restrict__ emb, const float* __restrict__ h0)
{
    long g = blockIdx.x * 256 + threadIdx.x;
    const long stride = 262144;
    float m0 = 0.f, m1 = 0.f, m2 = 0.f, m3 = 0.f;
    for (long i = g; i < 1048576L; i += stride) {
        m0 = fmaxf(m0, amax4(*(const float4*)&Wih[i * 4]));
        m1 = fmaxf(m1, amax4(*(const float4*)&Whh[i * 4]));
    }
    for (long i = g; i < 12800000L; i += stride)
        m2 = fmaxf(m2, amax4(*(const float4*)&emb[i * 4]));
    m3 = amax4(*(const float4*)&h0[g * 4]);
#pragma unroll
    for (int off = 16; off > 0; off >>= 1) {
        m0 = fmaxf(m0, __shfl_xor_sync(0xffffffffu, m0, off));
        m1 = fmaxf(m1, __shfl_xor_sync(0xffffffffu, m1, off));
        m2 = fmaxf(m2, __shfl_xor_sync(0xffffffffu, m2, off));
        m3 = fmaxf(m3, __shfl_xor_sync(0xffffffffu, m3, off));
    }
    if ((threadIdx.x & 31) == 0) {
        atomicMax(&d_absmax[0], __float_as_uint(m0));
        atomicMax(&d_absmax[1], __float_as_uint(m1));
        atomicMax(&d_absmax[2], __float_as_uint(m2));
        atomicMax(&d_absmax[3], __float_as_uint(m3));
    }
}

// ------------------------- init: quantize weights/emb/h0, layout c0 -------------------------
__global__ void init_quant(const float* __restrict__ Wih, const float* __restrict__ Whh,
                           const float* __restrict__ emb,
                           const float* __restrict__ h0,  const float* __restrict__ c0)
{
    int idx = blockIdx.x * 256 + threadIdx.x;
    float iWih = QMAXF / fmaxf(__uint_as_float(d_absmax[0]), 1e-20f);
    float iWhh = QMAXF / fmaxf(__uint_as_float(d_absmax[1]), 1e-20f);
    float iEmb = QMAXF / fmaxf(__uint_as_float(d_absmax[2]), 1e-20f);
    float iH0  = QMAXF / fmaxf(__uint_as_float(d_absmax[3]), 1e-20f);

    if (idx < 1048576) {
        quant16x4(*(const float4*)&Wih[idx * 4], iWih,
                  (char4*)&d_Wihq1[idx * 4], (char4*)&d_Wihq0[idx * 4]);
        quant16x4(*(const float4*)&Whh[idx * 4], iWhh,
                  (char4*)&d_Whhq1[idx * 4], (char4*)&d_Whhq0[idx * 4]);
    }
    for (long i = idx; i < 12800000L; i += 4194304L)
        quant16x4(*(const float4*)&emb[i * 4], iEmb,
                  (char4*)&d_embq1[i * 4], (char4*)&d_embq0[i * 4]);
    if (idx < 262144)
        quant16x4(*(const float4*)&h0[idx * 4], iH0,
                  (char4*)&d_hq1[0][idx * 4], (char4*)&d_hq0[0][idx * 4]);
    if (idx < 1048576) {
        // c0 -> fragment layout (16-warp geometry)
        int b = idx >> 10, hc = idx & 1023;
        int bm = b >> 7, rb = b & 127;
        int wm = rb >> 5, mf = (rb >> 4) & 1, rr = (rb >> 3) & 1, g = rb & 7;
        int bn = hc >> 5, hcl = hc & 31;
        int wn = hcl >> 3, tg = (hcl & 7) >> 1, e = hcl & 1;
        int warp = wn * 4 + wm, lane = g * 4 + tg, q = rr * 2 + e;
        int ci = (((bm * 32 + bn) * 16 + warp) * 2 + mf) * 128 + lane * 4 + q;
        d_Cfrag[ci] = c0[idx];
    }
    if (idx < 131072) d_logits[idx] = 0.0f;
}

// ------------------------- input GEMM: Xg = emb[x] @ W_ih^T + (b_ih + b_hh) -------------------------
__global__ void __launch_bounds__(512, 1) input_gemm(const int* __restrict__ x,
                                                     const float* __restrict__ b_ih,
                                                     const float* __restrict__ b_hh)
{
    extern __shared__ char smem[];
    uint32_t sb = smem_u32(smem);
    int tid = threadIdx.x;
    int bn = blockIdx.x, bm = blockIdx.y;
    int warp = tid >> 5, lane = tid & 31;
    int wm = warp & 3, wn = warp >> 2;
    int g = lane >> 2, tg = lane & 3;
    int hc0 = bn * 32;

    float sAB = (__uint_as_float(d_absmax[2]) / QMAXF) * (__uint_as_float(d_absmax[0]) / QMAXF);
    float sHIc = sAB * 65536.0f, sLOc = sAB * 256.0f;

    int* toks = (int*)(smem + 512);
    if (tid < 128) {
        int row = bm * 128 + tid;          // row = t*B + b
        toks[tid] = x[(row & 1023) * 64 + (row >> 10)];
    }
    __syncthreads();

    int r = tid >> 2, c = tid & 3;
    uint32_t offA = (uint32_t)(r * 80 + c * 16);
    size_t aoff = (size_t)toks[r] * 1024 + c * 16;
    size_t boff = (size_t)n_of(r, hc0) * 1024 + c * 16;

    uint32_t laneA = (uint32_t)((wm * 32 + (lane & 15)) * 80 + (lane >> 4) * 16);
    uint32_t laneB = (uint32_t)((wn * 32 + ((lane >> 4) << 3) + (lane & 7)) * 80
                                + ((lane >> 3) & 1) * 16);

    int acc1[2][4][4], acc2[2][4][4];
#pragma unroll
    for (int i = 0; i < 2; i++)
#pragma unroll
        for (int j = 0; j < 4; j++)
#pragma unroll
            for (int q = 0; q < 4; q++) { acc1[i][j][q] = 0; acc2[i][j][q] = 0; }

    // prefetch chunks 0..2 into stages 0..2
#pragma unroll
    for (int p = 0; p < 3; p++) {
        uint32_t st = sb + CTRL + p * STAGE;
        int k0 = p * 64;
        CP16(st +         offA, d_embq1 + aoff + k0);
        CP16(st + 10240 + offA, d_embq0 + aoff + k0);
        CP16(st + 20480 + offA, d_Wihq1 + boff + k0);
        CP16(st + 30720 + offA, d_Wihq0 + boff + k0);
        CP_COMMIT();
    }

    for (int kt = 0; kt < 16; kt++) {
        CP_WAIT2();
        __syncthreads();
        // prefetch chunk kt+3 BEFORE the MMA block so DMA overlaps compute
        if (kt + 3 < 16) {
            int k0 = (kt + 3) * 64;
            uint32_t st = sb + CTRL + ((kt + 3) & 3) * STAGE;
            CP16(st +         offA, d_embq1 + aoff + k0);
            CP16(st + 10240 + offA, d_embq0 + aoff + k0);
            CP16(st + 20480 + offA, d_Wihq1 + boff + k0);
            CP16(st + 30720 + offA, d_Wihq0 + boff + k0);
        }
        CP_COMMIT();
        uint32_t s0 = sb + CTRL + (kt & 3) * STAGE;
        gemm_chunk_i8(acc1, acc2, s0 + laneA, s0 + 10240 + laneA,
                                  s0 + 20480 + laneB, s0 + 30720 + laneB);
    }

    // epilogue: combine terms, add biases, store in fragment order
#pragma unroll
    for (int mf = 0; mf < 2; mf++)
#pragma unroll
        for (int nf = 0; nf < 4; nf++) {
            int n0 = nf * 1024 + hc0 + wn * 8 + 2 * tg;
            float be0 = b_ih[n0] + b_hh[n0];
            float be1 = b_ih[n0 + 1] + b_hh[n0 + 1];
            size_t off = ((((size_t)bm * 32 + bn) * 16 + warp) * 8 + mf * 4 + nf) * 128 + lane * 4;
            float4 v;
            v.x = sHIc * (float)acc1[mf][nf][0] + sLOc * (float)acc2[mf][nf][0] + be0;
            v.y = sHIc * (float)acc1[mf][nf][1] + sLOc * (float)acc2[mf][nf][1] + be1;
            v.z = sHIc * (float)acc1[mf][nf][2] + sLOc * (float)acc2[mf][nf][2] + be0;
            v.w = sHIc * (float)acc1[mf][nf][3] + sLOc * (float)acc2[mf][nf][3] + be1;
            *(float4*)&d_Xg[off] = v;
        }
}

// ------------------------- one recurrent step -------------------------
__global__ void __launch_bounds__(512, 1) step_kernel(int t,
                                                      const float* __restrict__ Wout,
                                                      const float* __restrict__ b_out,
                                                      float* __restrict__ out)
{
    extern __shared__ char smem[];
    uint32_t sb = smem_u32(smem);
    int tid = threadIdx.x;
    int bn = blockIdx.x, bm = blockIdx.y;
    int warp = tid >> 5, lane = tid & 31;
    int wm = warp & 3, wn = warp >> 2;
    int g = lane >> 2, tg = lane & 3;
    int m0 = bm * 128, hc0 = bn * 32;

    if (t > 0 && bn == 0 && bm == 0) {
        int tb = (t - 1) << 11;
        for (int i = tid; i < 1024; i += 512) {
            float l0 = d_logits[tb + i * 2 + 0] + b_out[0];
            float l1 = d_logits[tb + i * 2 + 1] + b_out[1];
            float mx = fmaxf(l0, l1);
            float lse = mx + logf(expf(l0 - mx) + expf(l1 - mx));
            out[tb + i * 2 + 0] = l0 - lse;
            out[tb + i * 2 + 1] = l1 - lse;
        }
    }

    float sh  = (t == 0) ? (__uint_as_float(d_absmax[3]) / QMAXF) : (1.0f / QMAXF);
    float sAB = sh * (__uint_as_float(d_absmax[1]) / QMAXF);
    float sHIc = sAB * 65536.0f, sLOc = sAB * 256.0f;

    const signed char* hQ1 = d_hq1[t & 1];
    const signed char* hQ0 = d_hq0[t & 1];
    signed char* nQ1 = d_hq1[(t + 1) & 1];
    signed char* nQ0 = d_hq0[(t + 1) & 1];

    float* ws = (float*)smem;   // 64 floats: [cls][hcL 0..31]
    if (tid < 64) ws[tid] = Wout[(tid >> 5) * 1024 + hc0 + (tid & 31)];
    __syncthreads();

    int r = tid >> 2, c = tid & 3;
    uint32_t offA = (uint32_t)(r * 80 + c * 16);
    size_t aoff = (size_t)(m0 + r) * 1024 + c * 16;
    size_t boff = (size_t)n_of(r, hc0) * 1024 + c * 16;

    uint32_t laneA = (uint32_t)((wm * 32 + (lane & 15)) * 80 + (lane >> 4) * 16);
    uint32_t laneB = (uint32_t)((wn * 32 + ((lane >> 4) << 3) + (lane & 7)) * 80
                                + ((lane >> 3) & 1) * 16);

    int acc1[2][4][4], acc2[2][4][4];
#pragma unroll
    for (int i = 0; i < 2; i++)
#pragma unroll
        for (int j = 0; j < 4; j++)
#pragma unroll
            for (int q = 0; q < 4; q++) { acc1[i][j][q] = 0; acc2[i][j][q] = 0; }

    // prefetch chunks 0..2 into stages 0..2
#pragma unroll
    for (int p = 0; p < 3; p++) {
        uint32_t st = sb + CTRL + p * STAGE;
        int k0 = p * 64;
        CP16(st +         offA, hQ1 + aoff + k0);
        CP16(st + 10240 + offA, hQ0 + aoff + k0);
        CP16(st + 20480 + offA, d_Whhq1 + boff + k0);
        CP16(st + 30720 + offA, d_Whhq0 + boff + k0);
        CP_COMMIT();
    }

    for (int kt = 0; kt < 16; kt++) {
        CP_WAIT2();
        __syncthreads();
        if (kt + 3 < 16) {
            int k0 = (kt + 3) * 64;
            uint32_t st = sb + CTRL + ((kt + 3) & 3) * STAGE;
            CP16(st +         offA, hQ1 + aoff + k0);
            CP16(st + 10240 + offA, hQ0 + aoff + k0);
            CP16(st + 20480 + offA, d_Whhq1 + boff + k0);
            CP16(st + 30720 + offA, d_Whhq0 + boff + k0);
        }
        CP_COMMIT();
        uint32_t s0 = sb + CTRL + (kt & 3) * STAGE;
        gemm_chunk_i8(acc1, acc2, s0 + laneA, s0 + 10240 + laneA,
                                  s0 + 20480 + laneB, s0 + 30720 + laneB);
    }

    // ---------------- fused LSTM epilogue ----------------
    size_t xgbase = ((((size_t)(t * 8 + bm) * 32 + bn) * 16 + warp) * 8) * 128 + lane * 4;
    size_t cbase  = ((((size_t)bm * 32 + bn) * 16 + warp) * 2) * 128 + lane * 4;

    float lsum[2][2][2];
#pragma unroll
    for (int i = 0; i < 2; i++)
#pragma unroll
        for (int j = 0; j < 2; j++) { lsum[i][j][0] = 0.0f; lsum[i][j][1] = 0.0f; }

#pragma unroll
    for (int mf = 0; mf < 2; mf++) {
        float4 CPc = *(const float4*)&d_Cfrag[cbase + mf * 128];
        float cprev[4] = {CPc.x, CPc.y, CPc.z, CPc.w};
        float4 PI = *(const float4*)&d_Xg[xgbase + (size_t)(mf * 4 + 0) * 128];
        float4 PF = *(const float4*)&d_Xg[xgbase + (size_t)(mf * 4 + 1) * 128];
        float4 PG = *(const float4*)&d_Xg[xgbase + (size_t)(mf * 4 + 2) * 128];
        float4 PO = *(const float4*)&d_Xg[xgbase + (size_t)(mf * 4 + 3) * 128];
        float pri[4] = {PI.x, PI.y, PI.z, PI.w};
        float prf[4] = {PF.x, PF.y, PF.z, PF.w};
        float prg[4] = {PG.x, PG.y, PG.z, PG.w};
        float pro[4] = {PO.x, PO.y, PO.z, PO.w};
        float cnew[4];
#pragma unroll
        for (int q = 0; q < 4; q++) {
            int rr = q >> 1, e = q & 1;
            float I = sHIc * (float)acc1[mf][0][q] + sLOc * (float)acc2[mf][0][q] + pri[q];
            float F = sHIc * (float)acc1[mf][1][q] + sLOc * (float)acc2[mf][1][q] + prf[q];
            float G = sHIc * (float)acc1[mf][2][q] + sLOc * (float)acc2[mf][2][q] + prg[q];
            float O = sHIc * (float)acc1[mf][3][q] + sLOc * (float)acc2[mf][3][q] + pro[q];
            float si = 1.0f / (1.0f + expf(-I));
            float sf = 1.0f / (1.0f + expf(-F));
            float so = 1.0f / (1.0f + expf(-O));
            float c2 = sf * cprev[q] + si * tanhf(G);
            float h2 = so * tanhf(c2);
            cnew[q] = c2;
            int b  = m0 + wm * 32 + mf * 16 + rr * 8 + g;
            int hcL = wn * 8 + 2 * tg + e;
            int hc = hc0 + hcL;
            int qh = __float2int_rn(h2 * QMAXF);
            int qh1 = (qh + 128) >> 8;
            nQ1[b * 1024 + hc] = (signed char)qh1;
            nQ0[b * 1024 + hc] = (signed char)(qh - (qh1 << 8));
            lsum[mf][rr][0] += c2 * ws[hcL];
            lsum[mf][rr][1] += c2 * ws[32 + hcL];
        }
        *(float4*)&d_Cfrag[cbase + mf * 128] = make_float4(cnew[0], cnew[1], cnew[2], cnew[3]);
    }

#pragma unroll
    for (int mf = 0; mf < 2; mf++)
#pragma unroll
        for (int rr = 0; rr < 2; rr++)
#pragma unroll
            for (int cls = 0; cls < 2; cls++) {
                float v = lsum[mf][rr][cls];
                v += __shfl_xor_sync(0xffffffffu, v, 1);
                v += __shfl_xor_sync(0xffffffffu, v, 2);
                if (tg == 0) {
                    int b = m0 + wm * 32 + mf * 16 + rr * 8 + g;
                    atomicAdd(&d_logits[(t << 11) + b * 2 + cls], v);
                }
            }
}

// ------------------------- finalize t=63 + out_final -------------------------
__global__ void final_kernel(const float* __restrict__ b_out, float* __restrict__ out)
{
    int i = blockIdx.x * 256 + threadIdx.x;
    if (i < 1024) {
        int tb = 63 << 11;
        float l0 = d_logits[tb + i * 2 + 0] + b_out[0];
        float l1 = d_logits[tb + i * 2 + 1] + b_out[1];
        float mx = fmaxf(l0, l1);
        float lse = mx + logf(expf(l0 - mx) + expf(l1 - mx));
        out[tb + i * 2 + 0] = l0 - lse;
        out[tb + i * 2 + 1] = l1 - lse;
        out[131072 + i * 2 + 0] = l0;
        out[131072 + i * 2 + 1] = l1;
    }
}

// ------------------------- launch -------------------------
extern "C" void kernel_launch(void* const* d_in, const int* in_sizes, int n_in,
                              void* d_out, int out_size)
{
    (void)in_sizes; (void)n_in; (void)out_size;
    const int*   x    = (const int*)d_in[0];
    const float* emb  = (const float*)d_in[1];
    const float* Wih  = (const float*)d_in[2];
    const float* Whh  = (const float*)d_in[3];
    const float* bih  = (const float*)d_in[4];
    const float* bhh  = (const float*)d_in[5];
    const float* Wout = (const float*)d_in[6];
    const float* bout = (const float*)d_in[7];
    const float* h0   = (const float*)d_in[8];
    const float* c0   = (const float*)d_in[9];
    float* out = (float*)d_out;

    cudaFuncSetAttribute(input_gemm, cudaFuncAttributeMaxDynamicSharedMemorySize, SMEM_BYTES);
    cudaFuncSetAttribute(step_kernel, cudaFuncAttributeMaxDynamicSharedMemorySize, SMEM_BYTES);

    zero_absmax<<<1, 32>>>();
    absmax_kernel<<<1024, 256>>>(Wih, Whh, emb, h0);
    init_quant<<<16384, 256>>>(Wih, Whh, emb, h0, c0);
    input_gemm<<<dim3(32, 512), 512, SMEM_BYTES>>>(x, bih, bhh);
    for (int t = 0; t < 64; t++)
        step_kernel<<<dim3(32, 8), 512, SMEM_BYTES>>>(t, Wout, bout, out);
    final_kernel<<<4, 256>>>(bout, out);
}

// round 14
// speedup vs baseline: 1.0782x; 1.0493x over previous
#include <cuda_runtime.h>
#include <cuda_bf16.h>
#include <cstdint>

// B=1024, T=64, E=H=1024, 4H=4096, NCLS=2, VOCAB=50000
// INT8 IMMA (m16n8k32.s8) fixed-point-split engine (R9 pipeline, unchanged):
//   x ~= s*(q1*256 + q0),  gates = sA*sB*(65536*T11 + 256*(T10+T01))
// 512 threads / 16 warps, warp tile 32x32, CTA tile 128x128 (K-chunk 64),
// 4-stage cp.async pipeline with ONE __syncthreads per chunk, ldmatrix loads,
// dependency-spaced MMA ordering, fused LSTM cell + classifier epilogue.
// NEW: each step launch also carries the input-GEMM tiles for time t+2
// (grid 32x16: bm<8 = recurrent, bm>=8 = input slice) -> wave packing.

#define CTRL  1024
#define STAGE 40960                    // A1 10240 | A0 10240 | B1 10240 | B0 10240
#define NSTAGE 4
#define SMEM_BYTES (CTRL + NSTAGE * STAGE)  // 164864
#define QMAXF 32512.0f

// ------------------------- static device scratch -------------------------
__device__ float d_Xg[268435456];      // pre-gates (+bias), fragment order
__device__ float d_Cfrag[1048576];     // cell state, fragment order
__device__ __align__(256) signed char d_hq1[2][1048576];
__device__ __align__(256) signed char d_hq0[2][1048576];
__device__ __align__(256) signed char d_Wihq1[4194304];
__device__ __align__(256) signed char d_Wihq0[4194304];
__device__ __align__(256) signed char d_Whhq1[4194304];
__device__ __align__(256) signed char d_Whhq0[4194304];
__device__ __align__(256) signed char d_embq1[51200000];
__device__ __align__(256) signed char d_embq0[51200000];
__device__ unsigned d_absmax[4];       // 0=Wih 1=Whh 2=emb 3=h0
__device__ float d_logits[131072];     // [T][B][2]

// ------------------------- helpers -------------------------
__device__ __forceinline__ uint32_t smem_u32(const void* p) {
    uint32_t a;
    asm("{ .reg .u64 t; cvta.to.shared.u64 t, %1; cvt.u32.u64 %0, t; }" : "=r"(a) : "l"(p));
    return a;
}

#define CP16(dst, src) \
    asm volatile("cp.async.cg.shared.global [%0], [%1], 16;" :: "r"(dst), "l"(src) : "memory")
#define CP_COMMIT() asm volatile("cp.async.commit_group;" ::: "memory")
#define CP_WAIT2()  asm volatile("cp.async.wait_group 2;" ::: "memory")

#define LDSM4(r0, r1, r2, r3, addr) \
    asm volatile("ldmatrix.sync.aligned.m8n8.x4.shared.b16 {%0,%1,%2,%3}, [%4];" \
        : "=r"(r0), "=r"(r1), "=r"(r2), "=r"(r3) : "r"(addr))

__device__ __forceinline__ void mma_s8(int* d, const uint32_t* a, const uint32_t* b) {
    asm volatile(
        "mma.sync.aligned.m16n8k32.row.col.s32.s8.s8.s32 "
        "{%0,%1,%2,%3}, {%4,%5,%6,%7}, {%8,%9}, {%0,%1,%2,%3};\n"
        : "+r"(d[0]), "+r"(d[1]), "+r"(d[2]), "+r"(d[3])
        : "r"(a[0]), "r"(a[1]), "r"(a[2]), "r"(a[3]), "r"(b[0]), "r"(b[1]));
}

// CTA-local col cl in [0,128) -> global n: cl = wn*32 + nf*8 + f, nf = gate
__device__ __forceinline__ int n_of(int cl, int hc0) {
    int wn_ = cl >> 5;
    int nf  = (cl >> 3) & 3;
    int f   = cl & 7;
    return nf * 1024 + hc0 + wn_ * 8 + f;
}

__device__ __forceinline__ void quant16(float v, float inv_s, signed char* a1, signed char* a0) {
    int q = __float2int_rn(v * inv_s);
    q = max(-32512, min(32512, q));
    int q1 = (q + 128) >> 8;
    *a1 = (signed char)q1;
    *a0 = (signed char)(q - (q1 << 8));
}
__device__ __forceinline__ void quant16x4(float4 v, float inv_s, char4* o1, char4* o0) {
    char4 c1, c0;
    quant16(v.x, inv_s, &c1.x, &c0.x);
    quant16(v.y, inv_s, &c1.y, &c0.y);
    quant16(v.z, inv_s, &c1.z, &c0.z);
    quant16(v.w, inv_s, &c1.w, &c0.w);
    *o1 = c1; *o0 = c0;
}

// one K=64 chunk (2x k32), 3-term split, warp tile 32x32, dependency-spaced order
__device__ __forceinline__ void gemm_chunk_i8(
    int acc1[2][4][4], int acc2[2][4][4],
    uint32_t aH, uint32_t aL, uint32_t bH, uint32_t bL)
{
#pragma unroll
    for (int ks = 0; ks < 2; ks++) {
        uint32_t off = ks * 32;
        uint32_t a1[2][4], a0[2][4], b1[8], b0[8];
        LDSM4(a1[0][0], a1[0][1], a1[0][2], a1[0][3], aH + off);
        LDSM4(a1[1][0], a1[1][1], a1[1][2], a1[1][3], aH + 1280 + off);
        LDSM4(a0[0][0], a0[0][1], a0[0][2], a0[0][3], aL + off);
        LDSM4(a0[1][0], a0[1][1], a0[1][2], a0[1][3], aL + 1280 + off);
        LDSM4(b1[0], b1[1], b1[2], b1[3], bH + off);
        LDSM4(b1[4], b1[5], b1[6], b1[7], bH + 1280 + off);
        LDSM4(b0[0], b0[1], b0[2], b0[3], bL + off);
        LDSM4(b0[4], b0[5], b0[6], b0[7], bL + 1280 + off);
        // 8x T11, then 8x T10, then 8x T01 -> same-acc distance = 8
#pragma unroll
        for (int mf = 0; mf < 2; mf++)
#pragma unroll
            for (int nf = 0; nf < 4; nf++)
                mma_s8(acc1[mf][nf], a1[mf], b1 + nf * 2);
#pragma unroll
        for (int mf = 0; mf < 2; mf++)
#pragma unroll
            for (int nf = 0; nf < 4; nf++)
                mma_s8(acc2[mf][nf], a1[mf], b0 + nf * 2);
#pragma unroll
        for (int mf = 0; mf < 2; mf++)
#pragma unroll
            for (int nf = 0; nf < 4; nf++)
                mma_s8(acc2[mf][nf], a0[mf], b1 + nf * 2);
    }
}

// ------------------------- input-GEMM tile body (exact R9 input_gemm) -------------------------
// Computes Xg rows [bm_g*128, bm_g*128+128) for n-tile bn.
__device__ __forceinline__ void input_tile_body(
    char* smem, uint32_t sb, int bm_g, int bn,
    const int* __restrict__ x, const float* __restrict__ b_ih, const float* __restrict__ b_hh)
{
    int tid = threadIdx.x;
    int warp = tid >> 5, lane = tid & 31;
    int wm = warp & 3, wn = warp >> 2;
    int tg = lane & 3;
    int hc0 = bn * 32;

    float sAB = (__uint_as_float(d_absmax[2]) / QMAXF) * (__uint_as_float(d_absmax[0]) / QMAXF);
    float sHIc = sAB * 65536.0f, sLOc = sAB * 256.0f;

    int* toks = (int*)(smem + 512);
    if (tid < 128) {
        int row = bm_g * 128 + tid;          // row = t*B + b
        toks[tid] = x[(row & 1023) * 64 + (row >> 10)];
    }
    __syncthreads();

    int r = tid >> 2, c = tid & 3;
    uint32_t offA = (uint32_t)(r * 80 + c * 16);
    size_t aoff = (size_t)toks[r] * 1024 + c * 16;
    size_t boff = (size_t)n_of(r, hc0) * 1024 + c * 16;

    uint32_t laneA = (uint32_t)((wm * 32 + (lane & 15)) * 80 + (lane >> 4) * 16);
    uint32_t laneB = (uint32_t)((wn * 32 + ((lane >> 4) << 3) + (lane & 7)) * 80
                                + ((lane >> 3) & 1) * 16);

    int acc1[2][4][4], acc2[2][4][4];
#pragma unroll
    for (int i = 0; i < 2; i++)
#pragma unroll
        for (int j = 0; j < 4; j++)
#pragma unroll
            for (int q = 0; q < 4; q++) { acc1[i][j][q] = 0; acc2[i][j][q] = 0; }

#pragma unroll
    for (int p = 0; p < 3; p++) {
        uint32_t st = sb + CTRL + p * STAGE;
        int k0 = p * 64;
        CP16(st +         offA, d_embq1 + aoff + k0);
        CP16(st + 10240 + offA, d_embq0 + aoff + k0);
        CP16(st + 20480 + offA, d_Wihq1 + boff + k0);
        CP16(st + 30720 + offA, d_Wihq0 + boff + k0);
        CP_COMMIT();
    }

    for (int kt = 0; kt < 16; kt++) {
        CP_WAIT2();
        __syncthreads();
        uint32_t s0 = sb + CTRL + (kt & 3) * STAGE;
        gemm_chunk_i8(acc1, acc2, s0 + laneA, s0 + 10240 + laneA,
                                  s0 + 20480 + laneB, s0 + 30720 + laneB);
        if (kt + 3 < 16) {
            int k0 = (kt + 3) * 64;
            uint32_t st = sb + CTRL + ((kt + 3) & 3) * STAGE;
            CP16(st +         offA, d_embq1 + aoff + k0);
            CP16(st + 10240 + offA, d_embq0 + aoff + k0);
            CP16(st + 20480 + offA, d_Wihq1 + boff + k0);
            CP16(st + 30720 + offA, d_Wihq0 + boff + k0);
        }
        CP_COMMIT();
    }

#pragma unroll
    for (int mf = 0; mf < 2; mf++)
#pragma unroll
        for (int nf = 0; nf < 4; nf++) {
            int n0 = nf * 1024 + hc0 + wn * 8 + 2 * tg;
            float be0 = b_ih[n0] + b_hh[n0];
            float be1 = b_ih[n0 + 1] + b_hh[n0 + 1];
            size_t off = ((((size_t)bm_g * 32 + bn) * 16 + warp) * 8 + mf * 4 + nf) * 128 + lane * 4;
            float4 v;
            v.x = sHIc * (float)acc1[mf][nf][0] + sLOc * (float)acc2[mf][nf][0] + be0;
            v.y = sHIc * (float)acc1[mf][nf][1] + sLOc * (float)acc2[mf][nf][1] + be1;
            v.z = sHIc * (float)acc1[mf][nf][2] + sLOc * (float)acc2[mf][nf][2] + be0;
            v.w = sHIc * (float)acc1[mf][nf][3] + sLOc * (float)acc2[mf][nf][3] + be1;
            *(float4*)&d_Xg[off] = v;
        }
}

// ------------------------- absmax pre-pass -------------------------
__global__ void zero_absmax() {
    if (threadIdx.x < 4) d_absmax[threadIdx.x] = 0u;
}

__device__ __forceinline__ float amax4(float4 v) {
    return fmaxf(fmaxf(fabsf(v.x), fabsf(v.y)), fmaxf(fabsf(v.z), fabsf(v.w)));
}

__global__ void absmax_kernel(const float* __restrict__ Wih, const float* __restrict__ Whh,
                              const float* __restrict__ emb, const float* __restrict__ h0)
{
    long g = blockIdx.x * 256 + threadIdx.x;
    const long stride = 262144;
    float m0 = 0.f, m1 = 0.f, m2 = 0.f, m3 = 0.f;
    for (long i = g; i < 1048576L; i += stride) {
        m0 = fmaxf(m0, amax4(*(const float4*)&Wih[i * 4]));
        m1 = fmaxf(m1, amax4(*(const float4*)&Whh[i * 4]));
    }
    for (long i = g; i < 12800000L; i += stride)
        m2 = fmaxf(m2, amax4(*(const float4*)&emb[i * 4]));
    m3 = amax4(*(const float4*)&h0[g * 4]);
#pragma unroll
    for (int off = 16; off > 0; off >>= 1) {
        m0 = fmaxf(m0, __shfl_xor_sync(0xffffffffu, m0, off));
        m1 = fmaxf(m1, __shfl_xor_sync(0xffffffffu, m1, off));
        m2 = fmaxf(m2, __shfl_xor_sync(0xffffffffu, m2, off));
        m3 = fmaxf(m3, __shfl_xor_sync(0xffffffffu, m3, off));
    }
    if ((threadIdx.x & 31) == 0) {
        atomicMax(&d_absmax[0], __float_as_uint(m0));
        atomicMax(&d_absmax[1], __float_as_uint(m1));
        atomicMax(&d_absmax[2], __float_as_uint(m2));
        atomicMax(&d_absmax[3], __float_as_uint(m3));
    }
}

// ------------------------- init: quantize weights/emb/h0, layout c0 -------------------------
__global__ void init_quant(const float* __restrict__ Wih, const float* __restrict__ Whh,
                           const float* __restrict__ emb,
                           const float* __restrict__ h0,  const float* __restrict__ c0)
{
    int idx = blockIdx.x * 256 + threadIdx.x;
    float iWih = QMAXF / fmaxf(__uint_as_float(d_absmax[0]), 1e-20f);
    float iWhh = QMAXF / fmaxf(__uint_as_float(d_absmax[1]), 1e-20f);
    float iEmb = QMAXF / fmaxf(__uint_as_float(d_absmax[2]), 1e-20f);
    float iH0  = QMAXF / fmaxf(__uint_as_float(d_absmax[3]), 1e-20f);

    if (idx < 1048576) {
        quant16x4(*(const float4*)&Wih[idx * 4], iWih,
                  (char4*)&d_Wihq1[idx * 4], (char4*)&d_Wihq0[idx * 4]);
        quant16x4(*(const float4*)&Whh[idx * 4], iWhh,
                  (char4*)&d_Whhq1[idx * 4], (char4*)&d_Whhq0[idx * 4]);
    }
    for (long i = idx; i < 12800000L; i += 4194304L)
        quant16x4(*(const float4*)&emb[i * 4], iEmb,
                  (char4*)&d_embq1[i * 4], (char4*)&d_embq0[i * 4]);
    if (idx < 262144)
        quant16x4(*(const float4*)&h0[idx * 4], iH0,
                  (char4*)&d_hq1[0][idx * 4], (char4*)&d_hq0[0][idx * 4]);
    if (idx < 1048576) {
        // c0 -> fragment layout (16-warp geometry)
        int b = idx >> 10, hc = idx & 1023;
        int bm = b >> 7, rb = b & 127;
        int wm = rb >> 5, mf = (rb >> 4) & 1, rr = (rb >> 3) & 1, g = rb & 7;
        int bn = hc >> 5, hcl = hc & 31;
        int wn = hcl >> 3, tg = (hcl & 7) >> 1, e = hcl & 1;
        int warp = wn * 4 + wm, lane = g * 4 + tg, q = rr * 2 + e;
        int ci = (((bm * 32 + bn) * 16 + warp) * 2 + mf) * 128 + lane * 4 + q;
        d_Cfrag[ci] = c0[idx];
    }
    if (idx < 131072) d_logits[idx] = 0.0f;
}

// ------------------------- pre-input GEMM: Xg for t in {0,1} -------------------------
__global__ void __launch_bounds__(512, 1) pre_input_gemm(const int* __restrict__ x,
                                                         const float* __restrict__ b_ih,
                                                         const float* __restrict__ b_hh)
{
    extern __shared__ char smem[];
    uint32_t sb = smem_u32(smem);
    input_tile_body(smem, sb, blockIdx.y, blockIdx.x, x, b_ih, b_hh);
}

// ------------------------- fused step + lookahead-input kernel -------------------------
__global__ void __launch_bounds__(512, 1) step_kernel(int t,
                                                      const int* __restrict__ x,
                                                      const float* __restrict__ b_ih,
                                                      const float* __restrict__ b_hh,
                                                      const float* __restrict__ Wout,
                                                      const float* __restrict__ b_out,
                                                      float* __restrict__ out)
{
    extern __shared__ char smem[];
    uint32_t sb = smem_u32(smem);
    int tid = threadIdx.x;
    int bn = blockIdx.x, bm = blockIdx.y;

    // --------- input-GEMM lookahead path (bm 8..15): Xg for time t+2 ---------
    if (bm >= 8) {
        int t2 = t + 2;
        if (t2 < 64)
            input_tile_body(smem, sb, t2 * 8 + (bm - 8), bn, x, b_ih, b_hh);
        return;
    }

    // --------- recurrent path (bm 0..7), exact R9 step body ---------
    int warp = tid >> 5, lane = tid & 31;
    int wm = warp & 3, wn = warp >> 2;
    int g = lane >> 2, tg = lane & 3;
    int m0 = bm * 128, hc0 = bn * 32;

    if (t > 0 && bn == 0 && bm == 0) {
        int tb = (t - 1) << 11;
        for (int i = tid; i < 1024; i += 512) {
            float l0 = d_logits[tb + i * 2 + 0] + b_out[0];
            float l1 = d_logits[tb + i * 2 + 1] + b_out[1];
            float mx = fmaxf(l0, l1);
            float lse = mx + logf(expf(l0 - mx) + expf(l1 - mx));
            out[tb + i * 2 + 0] = l0 - lse;
            out[tb + i * 2 + 1] = l1 - lse;
        }
    }

    float sh  = (t == 0) ? (__uint_as_float(d_absmax[3]) / QMAXF) : (1.0f / QMAXF);
    float sAB = sh * (__uint_as_float(d_absmax[1]) / QMAXF);
    float sHIc = sAB * 65536.0f, sLOc = sAB * 256.0f;

    const signed char* hQ1 = d_hq1[t & 1];
    const signed char* hQ0 = d_hq0[t & 1];
    signed char* nQ1 = d_hq1[(t + 1) & 1];
    signed char* nQ0 = d_hq0[(t + 1) & 1];

    float* ws = (float*)smem;   // 64 floats: [cls][hcL 0..31]
    if (tid < 64) ws[tid] = Wout[(tid >> 5) * 1024 + hc0 + (tid & 31)];
    __syncthreads();

    int r = tid >> 2, c = tid & 3;
    uint32_t offA = (uint32_t)(r * 80 + c * 16);
    size_t aoff = (size_t)(m0 + r) * 1024 + c * 16;
    size_t boff = (size_t)n_of(r, hc0) * 1024 + c * 16;

    uint32_t laneA = (uint32_t)((wm * 32 + (lane & 15)) * 80 + (lane >> 4) * 16);
    uint32_t laneB = (uint32_t)((wn * 32 + ((lane >> 4) << 3) + (lane & 7)) * 80
                                + ((lane >> 3) & 1) * 16);

    int acc1[2][4][4], acc2[2][4][4];
#pragma unroll
    for (int i = 0; i < 2; i++)
#pragma unroll
        for (int j = 0; j < 4; j++)
#pragma unroll
            for (int q = 0; q < 4; q++) { acc1[i][j][q] = 0; acc2[i][j][q] = 0; }

#pragma unroll
    for (int p = 0; p < 3; p++) {
        uint32_t st = sb + CTRL + p * STAGE;
        int k0 = p * 64;
        CP16(st +         offA, hQ1 + aoff + k0);
        CP16(st + 10240 + offA, hQ0 + aoff + k0);
        CP16(st + 20480 + offA, d_Whhq1 + boff + k0);
        CP16(st + 30720 + offA, d_Whhq0 + boff + k0);
        CP_COMMIT();
    }

    for (int kt = 0; kt < 16; kt++) {
        CP_WAIT2();
        __syncthreads();
        uint32_t s0 = sb + CTRL + (kt & 3) * STAGE;
        gemm_chunk_i8(acc1, acc2, s0 + laneA, s0 + 10240 + laneA,
                                  s0 + 20480 + laneB, s0 + 30720 + laneB);
        if (kt + 3 < 16) {
            int k0 = (kt + 3) * 64;
            uint32_t st = sb + CTRL + ((kt + 3) & 3) * STAGE;
            CP16(st +         offA, hQ1 + aoff + k0);
            CP16(st + 10240 + offA, hQ0 + aoff + k0);
            CP16(st + 20480 + offA, d_Whhq1 + boff + k0);
            CP16(st + 30720 + offA, d_Whhq0 + boff + k0);
        }
        CP_COMMIT();
    }

    // ---------------- fused LSTM epilogue ----------------
    size_t xgbase = ((((size_t)(t * 8 + bm) * 32 + bn) * 16 + warp) * 8) * 128 + lane * 4;
    size_t cbase  = ((((size_t)bm * 32 + bn) * 16 + warp) * 2) * 128 + lane * 4;

    float lsum[2][2][2];
#pragma unroll
    for (int i = 0; i < 2; i++)
#pragma unroll
        for (int j = 0; j < 2; j++) { lsum[i][j][0] = 0.0f; lsum[i][j][1] = 0.0f; }

#pragma unroll
    for (int mf = 0; mf < 2; mf++) {
        float4 CPc = *(const float4*)&d_Cfrag[cbase + mf * 128];
        float cprev[4] = {CPc.x, CPc.y, CPc.z, CPc.w};
        float4 PI = *(const float4*)&d_Xg[xgbase + (size_t)(mf * 4 + 0) * 128];
        float4 PF = *(const float4*)&d_Xg[xgbase + (size_t)(mf * 4 + 1) * 128];
        float4 PG = *(const float4*)&d_Xg[xgbase + (size_t)(mf * 4 + 2) * 128];
        float4 PO = *(const float4*)&d_Xg[xgbase + (size_t)(mf * 4 + 3) * 128];
        float pri[4] = {PI.x, PI.y, PI.z, PI.w};
        float prf[4] = {PF.x, PF.y, PF.z, PF.w};
        float prg[4] = {PG.x, PG.y, PG.z, PG.w};
        float pro[4] = {PO.x, PO.y, PO.z, PO.w};
        float cnew[4];
#pragma unroll
        for (int q = 0; q < 4; q++) {
            int rr = q >> 1, e = q & 1;
            float I = sHIc * (float)acc1[mf][0][q] + sLOc * (float)acc2[mf][0][q] + pri[q];
            float F = sHIc * (float)acc1[mf][1][q] + sLOc * (float)acc2[mf][1][q] + prf[q];
            float G = sHIc * (float)acc1[mf][2][q] + sLOc * (float)acc2[mf][2][q] + prg[q];
            float O = sHIc * (float)acc1[mf][3][q] + sLOc * (float)acc2[mf][3][q] + pro[q];
            float si = 1.0f / (1.0f + expf(-I));
            float sf = 1.0f / (1.0f + expf(-F));
            float so = 1.0f / (1.0f + expf(-O));
            float c2 = sf * cprev[q] + si * tanhf(G);
            float h2 = so * tanhf(c2);
            cnew[q] = c2;
            int b  = m0 + wm * 32 + mf * 16 + rr * 8 + g;
            int hcL = wn * 8 + 2 * tg + e;
            int hc = hc0 + hcL;
            int qh = __float2int_rn(h2 * QMAXF);
            int qh1 = (qh + 128) >> 8;
            nQ1[b * 1024 + hc] = (signed char)qh1;
            nQ0[b * 1024 + hc] = (signed char)(qh - (qh1 << 8));
            lsum[mf][rr][0] += c2 * ws[hcL];
            lsum[mf][rr][1] += c2 * ws[32 + hcL];
        }
        *(float4*)&d_Cfrag[cbase + mf * 128] = make_float4(cnew[0], cnew[1], cnew[2], cnew[3]);
    }

#pragma unroll
    for (int mf = 0; mf < 2; mf++)
#pragma unroll
        for (int rr = 0; rr < 2; rr++)
#pragma unroll
            for (int cls = 0; cls < 2; cls++) {
                float v = lsum[mf][rr][cls];
                v += __shfl_xor_sync(0xffffffffu, v, 1);
                v += __shfl_xor_sync(0xffffffffu, v, 2);
                if (tg == 0) {
                    int b = m0 + wm * 32 + mf * 16 + rr * 8 + g;
                    atomicAdd(&d_logits[(t << 11) + b * 2 + cls], v);
                }
            }
}

// ------------------------- finalize t=63 + out_final -------------------------
__global__ void final_kernel(const float* __restrict__ b_out, float* __restrict__ out)
{
    int i = blockIdx.x * 256 + threadIdx.x;
    if (i < 1024) {
        int tb = 63 << 11;
        float l0 = d_logits[tb + i * 2 + 0] + b_out[0];
        float l1 = d_logits[tb + i * 2 + 1] + b_out[1];
        float mx = fmaxf(l0, l1);
        float lse = mx + logf(expf(l0 - mx) + expf(l1 - mx));
        out[tb + i * 2 + 0] = l0 - lse;
        out[tb + i * 2 + 1] = l1 - lse;
        out[131072 + i * 2 + 0] = l0;
        out[131072 + i * 2 + 1] = l1;
    }
}

// ------------------------- launch -------------------------
extern "C" void kernel_launch(void* const* d_in, const int* in_sizes, int n_in,
                              void* d_out, int out_size)
{
    (void)in_sizes; (void)n_in; (void)out_size;
    const int*   x    = (const int*)d_in[0];
    const float* emb  = (const float*)d_in[1];
    const float* Wih  = (const float*)d_in[2];
    const float* Whh  = (const float*)d_in[3];
    const float* bih  = (const float*)d_in[4];
    const float* bhh  = (const float*)d_in[5];
    const float* Wout = (const float*)d_in[6];
    const float* bout = (const float*)d_in[7];
    const float* h0   = (const float*)d_in[8];
    const float* c0   = (const float*)d_in[9];
    float* out = (float*)d_out;

    cudaFuncSetAttribute(pre_input_gemm, cudaFuncAttributeMaxDynamicSharedMemorySize, SMEM_BYTES);
    cudaFuncSetAttribute(step_kernel, cudaFuncAttributeMaxDynamicSharedMemorySize, SMEM_BYTES);

    zero_absmax<<<1, 32>>>();
    absmax_kernel<<<1024, 256>>>(Wih, Whh, emb, h0);
    init_quant<<<16384, 256>>>(Wih, Whh, emb, h0, c0);
    pre_input_gemm<<<dim3(32, 16), 512, SMEM_BYTES>>>(x, bih, bhh);   // Xg for t=0,1
    for (int t = 0; t < 64; t++)
        step_kernel<<<dim3(32, 16), 512, SMEM_BYTES>>>(t, x, bih, bhh, Wout, bout, out);
    final_kernel<<<4, 256>>>(bout, out);
}

// round 15
// speedup vs baseline: 1.2680x; 1.1761x over previous
#include <cuda_runtime.h>
#include <cuda_bf16.h>
#include <cstdint>

// B=1024, T=64, E=H=1024, 4H=4096, NCLS=2, VOCAB=50000
// INT8 IMMA (m16n8k32.s8) fixed-point-split engine (R9 pipeline, frozen):
//   x ~= s*(q1*256 + q0),  gates = sA*sB*(65536*T11 + 256*(T10+T01))
// 512 threads / 16 warps, warp tile 32x32, CTA tile 128x128 (K-chunk 64),
// 4-stage cp.async pipeline, ONE __syncthreads per chunk, ldmatrix loads,
// dependency-spaced MMA ordering, fused LSTM cell + classifier epilogue.
// NEW: input GEMM sliced per-t on a second stream; event slice_t -> step_t.
// Input CTAs fill SM idle time of the sequential step chain (fork/join capture).

#define CTRL  1024
#define STAGE 40960                    // A1 10240 | A0 10240 | B1 10240 | B0 10240
#define NSTAGE 4
#define SMEM_BYTES (CTRL + NSTAGE * STAGE)  // 164864
#define QMAXF 32512.0f

// ------------------------- static device scratch -------------------------
__device__ float d_Xg[268435456];      // pre-gates (+bias), fragment order
__device__ float d_Cfrag[1048576];     // cell state, fragment order
__device__ __align__(256) signed char d_hq1[2][1048576];
__device__ __align__(256) signed char d_hq0[2][1048576];
__device__ __align__(256) signed char d_Wihq1[4194304];
__device__ __align__(256) signed char d_Wihq0[4194304];
__device__ __align__(256) signed char d_Whhq1[4194304];
__device__ __align__(256) signed char d_Whhq0[4194304];
__device__ __align__(256) signed char d_embq1[51200000];
__device__ __align__(256) signed char d_embq0[51200000];
__device__ unsigned d_absmax[4];       // 0=Wih 1=Whh 2=emb 3=h0
__device__ float d_logits[131072];     // [T][B][2]

// ------------------------- helpers -------------------------
__device__ __forceinline__ uint32_t smem_u32(const void* p) {
    uint32_t a;
    asm("{ .reg .u64 t; cvta.to.shared.u64 t, %1; cvt.u32.u64 %0, t; }" : "=r"(a) : "l"(p));
    return a;
}

#define CP16(dst, src) \
    asm volatile("cp.async.cg.shared.global [%0], [%1], 16;" :: "r"(dst), "l"(src) : "memory")
#define CP_COMMIT() asm volatile("cp.async.commit_group;" ::: "memory")
#define CP_WAIT2()  asm volatile("cp.async.wait_group 2;" ::: "memory")

#define LDSM4(r0, r1, r2, r3, addr) \
    asm volatile("ldmatrix.sync.aligned.m8n8.x4.shared.b16 {%0,%1,%2,%3}, [%4];" \
        : "=r"(r0), "=r"(r1), "=r"(r2), "=r"(r3) : "r"(addr))

__device__ __forceinline__ void mma_s8(int* d, const uint32_t* a, const uint32_t* b) {
    asm volatile(
        "mma.sync.aligned.m16n8k32.row.col.s32.s8.s8.s32 "
        "{%0,%1,%2,%3}, {%4,%5,%6,%7}, {%8,%9}, {%0,%1,%2,%3};\n"
        : "+r"(d[0]), "+r"(d[1]), "+r"(d[2]), "+r"(d[3])
        : "r"(a[0]), "r"(a[1]), "r"(a[2]), "r"(a[3]), "r"(b[0]), "r"(b[1]));
}

// CTA-local col cl in [0,128) -> global n: cl = wn*32 + nf*8 + f, nf = gate
__device__ __forceinline__ int n_of(int cl, int hc0) {
    int wn_ = cl >> 5;
    int nf  = (cl >> 3) & 3;
    int f   = cl & 7;
    return nf * 1024 + hc0 + wn_ * 8 + f;
}

__device__ __forceinline__ void quant16(float v, float inv_s, signed char* a1, signed char* a0) {
    int q = __float2int_rn(v * inv_s);
    q = max(-32512, min(32512, q));
    int q1 = (q + 128) >> 8;
    *a1 = (signed char)q1;
    *a0 = (signed char)(q - (q1 << 8));
}
__device__ __forceinline__ void quant16x4(float4 v, float inv_s, char4* o1, char4* o0) {
    char4 c1, c0;
    quant16(v.x, inv_s, &c1.x, &c0.x);
    quant16(v.y, inv_s, &c1.y, &c0.y);
    quant16(v.z, inv_s, &c1.z, &c0.z);
    quant16(v.w, inv_s, &c1.w, &c0.w);
    *o1 = c1; *o0 = c0;
}

// one K=64 chunk (2x k32), 3-term split, warp tile 32x32, dependency-spaced order
__device__ __forceinline__ void gemm_chunk_i8(
    int acc1[2][4][4], int acc2[2][4][4],
    uint32_t aH, uint32_t aL, uint32_t bH, uint32_t bL)
{
#pragma unroll
    for (int ks = 0; ks < 2; ks++) {
        uint32_t off = ks * 32;
        uint32_t a1[2][4], a0[2][4], b1[8], b0[8];
        LDSM4(a1[0][0], a1[0][1], a1[0][2], a1[0][3], aH + off);
        LDSM4(a1[1][0], a1[1][1], a1[1][2], a1[1][3], aH + 1280 + off);
        LDSM4(a0[0][0], a0[0][1], a0[0][2], a0[0][3], aL + off);
        LDSM4(a0[1][0], a0[1][1], a0[1][2], a0[1][3], aL + 1280 + off);
        LDSM4(b1[0], b1[1], b1[2], b1[3], bH + off);
        LDSM4(b1[4], b1[5], b1[6], b1[7], bH + 1280 + off);
        LDSM4(b0[0], b0[1], b0[2], b0[3], bL + off);
        LDSM4(b0[4], b0[5], b0[6], b0[7], bL + 1280 + off);
        // 8x T11, then 8x T10, then 8x T01 -> same-acc distance = 8
#pragma unroll
        for (int mf = 0; mf < 2; mf++)
#pragma unroll
            for (int nf = 0; nf < 4; nf++)
                mma_s8(acc1[mf][nf], a1[mf], b1 + nf * 2);
#pragma unroll
        for (int mf = 0; mf < 2; mf++)
#pragma unroll
            for (int nf = 0; nf < 4; nf++)
                mma_s8(acc2[mf][nf], a1[mf], b0 + nf * 2);
#pragma unroll
        for (int mf = 0; mf < 2; mf++)
#pragma unroll
            for (int nf = 0; nf < 4; nf++)
                mma_s8(acc2[mf][nf], a0[mf], b1 + nf * 2);
    }
}

// ------------------------- absmax pre-pass -------------------------
__global__ void zero_absmax() {
    if (threadIdx.x < 4) d_absmax[threadIdx.x] = 0u;
}

__device__ __forceinline__ float amax4(float4 v) {
    return fmaxf(fmaxf(fabsf(v.x), fabsf(v.y)), fmaxf(fabsf(v.z), fabsf(v.w)));
}

__global__ void absmax_kernel(const float* __restrict__ Wih, const float* __restrict__ Whh,
                              const float* __restrict__ emb, const float* __restrict__ h0)
{
    long g = blockIdx.x * 256 + threadIdx.x;
    const long stride = 262144;
    float m0 = 0.f, m1 = 0.f, m2 = 0.f, m3 = 0.f;
    for (long i = g; i < 1048576L; i += stride) {
        m0 = fmaxf(m0, amax4(*(const float4*)&Wih[i * 4]));
        m1 = fmaxf(m1, amax4(*(const float4*)&Whh[i * 4]));
    }
    for (long i = g; i < 12800000L; i += stride)
        m2 = fmaxf(m2, amax4(*(const float4*)&emb[i * 4]));
    m3 = amax4(*(const float4*)&h0[g * 4]);
#pragma unroll
    for (int off = 16; off > 0; off >>= 1) {
        m0 = fmaxf(m0, __shfl_xor_sync(0xffffffffu, m0, off));
        m1 = fmaxf(m1, __shfl_xor_sync(0xffffffffu, m1, off));
        m2 = fmaxf(m2, __shfl_xor_sync(0xffffffffu, m2, off));
        m3 = fmaxf(m3, __shfl_xor_sync(0xffffffffu, m3, off));
    }
    if ((threadIdx.x & 31) == 0) {
        atomicMax(&d_absmax[0], __float_as_uint(m0));
        atomicMax(&d_absmax[1], __float_as_uint(m1));
        atomicMax(&d_absmax[2], __float_as_uint(m2));
        atomicMax(&d_absmax[3], __float_as_uint(m3));
    }
}

// ------------------------- init: quantize weights/emb/h0, layout c0 -------------------------
__global__ void init_quant(const float* __restrict__ Wih, const float* __restrict__ Whh,
                           const float* __restrict__ emb,
                           const float* __restrict__ h0,  const float* __restrict__ c0)
{
    int idx = blockIdx.x * 256 + threadIdx.x;
    float iWih = QMAXF / fmaxf(__uint_as_float(d_absmax[0]), 1e-20f);
    float iWhh = QMAXF / fmaxf(__uint_as_float(d_absmax[1]), 1e-20f);
    float iEmb = QMAXF / fmaxf(__uint_as_float(d_absmax[2]), 1e-20f);
    float iH0  = QMAXF / fmaxf(__uint_as_float(d_absmax[3]), 1e-20f);

    if (idx < 1048576) {
        quant16x4(*(const float4*)&Wih[idx * 4], iWih,
                  (char4*)&d_Wihq1[idx * 4], (char4*)&d_Wihq0[idx * 4]);
        quant16x4(*(const float4*)&Whh[idx * 4], iWhh,
                  (char4*)&d_Whhq1[idx * 4], (char4*)&d_Whhq0[idx * 4]);
    }
    for (long i = idx; i < 12800000L; i += 4194304L)
        quant16x4(*(const float4*)&emb[i * 4], iEmb,
                  (char4*)&d_embq1[i * 4], (char4*)&d_embq0[i * 4]);
    if (idx < 262144)
        quant16x4(*(const float4*)&h0[idx * 4], iH0,
                  (char4*)&d_hq1[0][idx * 4], (char4*)&d_hq0[0][idx * 4]);
    if (idx < 1048576) {
        // c0 -> fragment layout (16-warp geometry)
        int b = idx >> 10, hc = idx & 1023;
        int bm = b >> 7, rb = b & 127;
        int wm = rb >> 5, mf = (rb >> 4) & 1, rr = (rb >> 3) & 1, g = rb & 7;
        int bn = hc >> 5, hcl = hc & 31;
        int wn = hcl >> 3, tg = (hcl & 7) >> 1, e = hcl & 1;
        int warp = wn * 4 + wm, lane = g * 4 + tg, q = rr * 2 + e;
        int ci = (((bm * 32 + bn) * 16 + warp) * 2 + mf) * 128 + lane * 4 + q;
        d_Cfrag[ci] = c0[idx];
    }
    if (idx < 131072) d_logits[idx] = 0.0f;
}

// ------------------------- input GEMM slice for one t: Xg[t*B ...] -------------------------
__global__ void __launch_bounds__(512, 1) input_slice(int t,
                                                      const int* __restrict__ x,
                                                      const float* __restrict__ b_ih,
                                                      const float* __restrict__ b_hh)
{
    extern __shared__ char smem[];
    uint32_t sb = smem_u32(smem);
    int tid = threadIdx.x;
    int bn = blockIdx.x;
    int bm_g = t * 8 + blockIdx.y;       // global 128-row tile index
    int warp = tid >> 5, lane = tid & 31;
    int wm = warp & 3, wn = warp >> 2;
    int tg = lane & 3;
    int hc0 = bn * 32;

    float sAB = (__uint_as_float(d_absmax[2]) / QMAXF) * (__uint_as_float(d_absmax[0]) / QMAXF);
    float sHIc = sAB * 65536.0f, sLOc = sAB * 256.0f;

    int* toks = (int*)(smem + 512);
    if (tid < 128) {
        int row = bm_g * 128 + tid;      // row = t*B + b
        toks[tid] = x[(row & 1023) * 64 + (row >> 10)];
    }
    __syncthreads();

    int r = tid >> 2, c = tid & 3;
    uint32_t offA = (uint32_t)(r * 80 + c * 16);
    size_t aoff = (size_t)toks[r] * 1024 + c * 16;
    size_t boff = (size_t)n_of(r, hc0) * 1024 + c * 16;

    uint32_t laneA = (uint32_t)((wm * 32 + (lane & 15)) * 80 + (lane >> 4) * 16);
    uint32_t laneB = (uint32_t)((wn * 32 + ((lane >> 4) << 3) + (lane & 7)) * 80
                                + ((lane >> 3) & 1) * 16);

    int acc1[2][4][4], acc2[2][4][4];
#pragma unroll
    for (int i = 0; i < 2; i++)
#pragma unroll
        for (int j = 0; j < 4; j++)
#pragma unroll
            for (int q = 0; q < 4; q++) { acc1[i][j][q] = 0; acc2[i][j][q] = 0; }

#pragma unroll
    for (int p = 0; p < 3; p++) {
        uint32_t st = sb + CTRL + p * STAGE;
        int k0 = p * 64;
        CP16(st +         offA, d_embq1 + aoff + k0);
        CP16(st + 10240 + offA, d_embq0 + aoff + k0);
        CP16(st + 20480 + offA, d_Wihq1 + boff + k0);
        CP16(st + 30720 + offA, d_Wihq0 + boff + k0);
        CP_COMMIT();
    }

    for (int kt = 0; kt < 16; kt++) {
        CP_WAIT2();
        __syncthreads();
        uint32_t s0 = sb + CTRL + (kt & 3) * STAGE;
        gemm_chunk_i8(acc1, acc2, s0 + laneA, s0 + 10240 + laneA,
                                  s0 + 20480 + laneB, s0 + 30720 + laneB);
        if (kt + 3 < 16) {
            int k0 = (kt + 3) * 64;
            uint32_t st = sb + CTRL + ((kt + 3) & 3) * STAGE;
            CP16(st +         offA, d_embq1 + aoff + k0);
            CP16(st + 10240 + offA, d_embq0 + aoff + k0);
            CP16(st + 20480 + offA, d_Wihq1 + boff + k0);
            CP16(st + 30720 + offA, d_Wihq0 + boff + k0);
        }
        CP_COMMIT();
    }

#pragma unroll
    for (int mf = 0; mf < 2; mf++)
#pragma unroll
        for (int nf = 0; nf < 4; nf++) {
            int n0 = nf * 1024 + hc0 + wn * 8 + 2 * tg;
            float be0 = b_ih[n0] + b_hh[n0];
            float be1 = b_ih[n0 + 1] + b_hh[n0 + 1];
            size_t off = ((((size_t)bm_g * 32 + bn) * 16 + warp) * 8 + mf * 4 + nf) * 128 + lane * 4;
            float4 v;
            v.x = sHIc * (float)acc1[mf][nf][0] + sLOc * (float)acc2[mf][nf][0] + be0;
            v.y = sHIc * (float)acc1[mf][nf][1] + sLOc * (float)acc2[mf][nf][1] + be1;
            v.z = sHIc * (float)acc1[mf][nf][2] + sLOc * (float)acc2[mf][nf][2] + be0;
            v.w = sHIc * (float)acc1[mf][nf][3] + sLOc * (float)acc2[mf][nf][3] + be1;
            *(float4*)&d_Xg[off] = v;
        }
}

// ------------------------- one recurrent step (R9, unchanged) -------------------------
__global__ void __launch_bounds__(512, 1) step_kernel(int t,
                                                      const float* __restrict__ Wout,
                                                      const float* __restrict__ b_out,
                                                      float* __restrict__ out)
{
    extern __shared__ char smem[];
    uint32_t sb = smem_u32(smem);
    int tid = threadIdx.x;
    int bn = blockIdx.x, bm = blockIdx.y;
    int warp = tid >> 5, lane = tid & 31;
    int wm = warp & 3, wn = warp >> 2;
    int g = lane >> 2, tg = lane & 3;
    int m0 = bm * 128, hc0 = bn * 32;

    if (t > 0 && bn == 0 && bm == 0) {
        int tb = (t - 1) << 11;
        for (int i = tid; i < 1024; i += 512) {
            float l0 = d_logits[tb + i * 2 + 0] + b_out[0];
            float l1 = d_logits[tb + i * 2 + 1] + b_out[1];
            float mx = fmaxf(l0, l1);
            float lse = mx + logf(expf(l0 - mx) + expf(l1 - mx));
            out[tb + i * 2 + 0] = l0 - lse;
            out[tb + i * 2 + 1] = l1 - lse;
        }
    }

    float sh  = (t == 0) ? (__uint_as_float(d_absmax[3]) / QMAXF) : (1.0f / QMAXF);
    float sAB = sh * (__uint_as_float(d_absmax[1]) / QMAXF);
    float sHIc = sAB * 65536.0f, sLOc = sAB * 256.0f;

    const signed char* hQ1 = d_hq1[t & 1];
    const signed char* hQ0 = d_hq0[t & 1];
    signed char* nQ1 = d_hq1[(t + 1) & 1];
    signed char* nQ0 = d_hq0[(t + 1) & 1];

    float* ws = (float*)smem;   // 64 floats: [cls][hcL 0..31]
    if (tid < 64) ws[tid] = Wout[(tid >> 5) * 1024 + hc0 + (tid & 31)];
    __syncthreads();

    int r = tid >> 2, c = tid & 3;
    uint32_t offA = (uint32_t)(r * 80 + c * 16);
    size_t aoff = (size_t)(m0 + r) * 1024 + c * 16;
    size_t boff = (size_t)n_of(r, hc0) * 1024 + c * 16;

    uint32_t laneA = (uint32_t)((wm * 32 + (lane & 15)) * 80 + (lane >> 4) * 16);
    uint32_t laneB = (uint32_t)((wn * 32 + ((lane >> 4) << 3) + (lane & 7)) * 80
                                + ((lane >> 3) & 1) * 16);

    int acc1[2][4][4], acc2[2][4][4];
#pragma unroll
    for (int i = 0; i < 2; i++)
#pragma unroll
        for (int j = 0; j < 4; j++)
#pragma unroll
            for (int q = 0; q < 4; q++) { acc1[i][j][q] = 0; acc2[i][j][q] = 0; }

#pragma unroll
    for (int p = 0; p < 3; p++) {
        uint32_t st = sb + CTRL + p * STAGE;
        int k0 = p * 64;
        CP16(st +         offA, hQ1 + aoff + k0);
        CP16(st + 10240 + offA, hQ0 + aoff + k0);
        CP16(st + 20480 + offA, d_Whhq1 + boff + k0);
        CP16(st + 30720 + offA, d_Whhq0 + boff + k0);
        CP_COMMIT();
    }

    for (int kt = 0; kt < 16; kt++) {
        CP_WAIT2();
        __syncthreads();
        uint32_t s0 = sb + CTRL + (kt & 3) * STAGE;
        gemm_chunk_i8(acc1, acc2, s0 + laneA, s0 + 10240 + laneA,
                                  s0 + 20480 + laneB, s0 + 30720 + laneB);
        if (kt + 3 < 16) {
            int k0 = (kt + 3) * 64;
            uint32_t st = sb + CTRL + ((kt + 3) & 3) * STAGE;
            CP16(st +         offA, hQ1 + aoff + k0);
            CP16(st + 10240 + offA, hQ0 + aoff + k0);
            CP16(st + 20480 + offA, d_Whhq1 + boff + k0);
            CP16(st + 30720 + offA, d_Whhq0 + boff + k0);
        }
        CP_COMMIT();
    }

    // ---------------- fused LSTM epilogue ----------------
    size_t xgbase = ((((size_t)(t * 8 + bm) * 32 + bn) * 16 + warp) * 8) * 128 + lane * 4;
    size_t cbase  = ((((size_t)bm * 32 + bn) * 16 + warp) * 2) * 128 + lane * 4;

    float lsum[2][2][2];
#pragma unroll
    for (int i = 0; i < 2; i++)
#pragma unroll
        for (int j = 0; j < 2; j++) { lsum[i][j][0] = 0.0f; lsum[i][j][1] = 0.0f; }

#pragma unroll
    for (int mf = 0; mf < 2; mf++) {
        float4 CPc = *(const float4*)&d_Cfrag[cbase + mf * 128];
        float cprev[4] = {CPc.x, CPc.y, CPc.z, CPc.w};
        float4 PI = *(const float4*)&d_Xg[xgbase + (size_t)(mf * 4 + 0) * 128];
        float4 PF = *(const float4*)&d_Xg[xgbase + (size_t)(mf * 4 + 1) * 128];
        float4 PG = *(const float4*)&d_Xg[xgbase + (size_t)(mf * 4 + 2) * 128];
        float4 PO = *(const float4*)&d_Xg[xgbase + (size_t)(mf * 4 + 3) * 128];
        float pri[4] = {PI.x, PI.y, PI.z, PI.w};
        float prf[4] = {PF.x, PF.y, PF.z, PF.w};
        float prg[4] = {PG.x, PG.y, PG.z, PG.w};
        float pro[4] = {PO.x, PO.y, PO.z, PO.w};
        float cnew[4];
#pragma unroll
        for (int q = 0; q < 4; q++) {
            int rr = q >> 1, e = q & 1;
            float I = sHIc * (float)acc1[mf][0][q] + sLOc * (float)acc2[mf][0][q] + pri[q];
            float F = sHIc * (float)acc1[mf][1][q] + sLOc * (float)acc2[mf][1][q] + prf[q];
            float G = sHIc * (float)acc1[mf][2][q] + sLOc * (float)acc2[mf][2][q] + prg[q];
            float O = sHIc * (float)acc1[mf][3][q] + sLOc * (float)acc2[mf][3][q] + pro[q];
            float si = 1.0f / (1.0f + expf(-I));
            float sf = 1.0f / (1.0f + expf(-F));
            float so = 1.0f / (1.0f + expf(-O));
            float c2 = sf * cprev[q] + si * tanhf(G);
            float h2 = so * tanhf(c2);
            cnew[q] = c2;
            int b  = m0 + wm * 32 + mf * 16 + rr * 8 + g;
            int hcL = wn * 8 + 2 * tg + e;
            int hc = hc0 + hcL;
            int qh = __float2int_rn(h2 * QMAXF);
            int qh1 = (qh + 128) >> 8;
            nQ1[b * 1024 + hc] = (signed char)qh1;
            nQ0[b * 1024 + hc] = (signed char)(qh - (qh1 << 8));
            lsum[mf][rr][0] += c2 * ws[hcL];
            lsum[mf][rr][1] += c2 * ws[32 + hcL];
        }
        *(float4*)&d_Cfrag[cbase + mf * 128] = make_float4(cnew[0], cnew[1], cnew[2], cnew[3]);
    }

#pragma unroll
    for (int mf = 0; mf < 2; mf++)
#pragma unroll
        for (int rr = 0; rr < 2; rr++)
#pragma unroll
            for (int cls = 0; cls < 2; cls++) {
                float v = lsum[mf][rr][cls];
                v += __shfl_xor_sync(0xffffffffu, v, 1);
                v += __shfl_xor_sync(0xffffffffu, v, 2);
                if (tg == 0) {
                    int b = m0 + wm * 32 + mf * 16 + rr * 8 + g;
                    atomicAdd(&d_logits[(t << 11) + b * 2 + cls], v);
                }
            }
}

// ------------------------- finalize t=63 + out_final -------------------------
__global__ void final_kernel(const float* __restrict__ b_out, float* __restrict__ out)
{
    int i = blockIdx.x * 256 + threadIdx.x;
    if (i < 1024) {
        int tb = 63 << 11;
        float l0 = d_logits[tb + i * 2 + 0] + b_out[0];
        float l1 = d_logits[tb + i * 2 + 1] + b_out[1];
        float mx = fmaxf(l0, l1);
        float lse = mx + logf(expf(l0 - mx) + expf(l1 - mx));
        out[tb + i * 2 + 0] = l0 - lse;
        out[tb + i * 2 + 1] = l1 - lse;
        out[131072 + i * 2 + 0] = l0;
        out[131072 + i * 2 + 1] = l1;
    }
}

// ------------------------- launch (fork/join over two streams) -------------------------
extern "C" void kernel_launch(void* const* d_in, const int* in_sizes, int n_in,
                              void* d_out, int out_size)
{
    (void)in_sizes; (void)n_in; (void)out_size;
    const int*   x    = (const int*)d_in[0];
    const float* emb  = (const float*)d_in[1];
    const float* Wih  = (const float*)d_in[2];
    const float* Whh  = (const float*)d_in[3];
    const float* bih  = (const float*)d_in[4];
    const float* bhh  = (const float*)d_in[5];
    const float* Wout = (const float*)d_in[6];
    const float* bout = (const float*)d_in[7];
    const float* h0   = (const float*)d_in[8];
    const float* c0   = (const float*)d_in[9];
    float* out = (float*)d_out;

    cudaFuncSetAttribute(input_slice, cudaFuncAttributeMaxDynamicSharedMemorySize, SMEM_BYTES);
    cudaFuncSetAttribute(step_kernel, cudaFuncAttributeMaxDynamicSharedMemorySize, SMEM_BYTES);

    // host-side objects: created at capture time only (graph replays don't rerun this code)
    cudaStream_t s2;
    cudaStreamCreateWithFlags(&s2, cudaStreamNonBlocking);
    cudaEvent_t evFork;
    cudaEventCreateWithFlags(&evFork, cudaEventDisableTiming);
    static cudaEvent_t evSlice[64];
    for (int t = 0; t < 64; t++)
        cudaEventCreateWithFlags(&evSlice[t], cudaEventDisableTiming);

    // init phase on main stream
    zero_absmax<<<1, 32>>>();
    absmax_kernel<<<1024, 256>>>(Wih, Whh, emb, h0);
    init_quant<<<16384, 256>>>(Wih, Whh, emb, h0, c0);

    // fork: s2 depends on init
    cudaEventRecord(evFork, 0);
    cudaStreamWaitEvent(s2, evFork, 0);

    // input slices on s2 (in t order), each records its completion event
    for (int t = 0; t < 64; t++) {
        input_slice<<<dim3(32, 8), 512, SMEM_BYTES, s2>>>(t, x, bih, bhh);
        cudaEventRecord(evSlice[t], s2);
    }

    // step chain on main stream; step t joins on slice t
    for (int t = 0; t < 64; t++) {
        cudaStreamWaitEvent(0, evSlice[t], 0);
        step_kernel<<<dim3(32, 8), 512, SMEM_BYTES>>>(t, Wout, bout, out);
    }
    final_kernel<<<4, 256>>>(bout, out);
}

// round 16
// speedup vs baseline: 1.2777x; 1.0077x over previous
#include <cuda_runtime.h>
#include <cuda_bf16.h>
#include <cstdint>

// B=1024, T=64, E=H=1024, 4H=4096, NCLS=2, VOCAB=50000
// INT8 IMMA (m16n8k32.s8) fixed-point-split engine.
//   x ~= s*(q1*256 + q0),  gates = sA*sB*(65536*T11 + 256*(T10+T01))
// R10 geometry for BOTH kernels: 256 threads / 8 warps (wm2 x wn4), CTA tile
// 64x128, warp tile 32x32, 3-stage cp.async pipeline, ldmatrix loads,
// dependency-spaced MMA ordering, fused LSTM epilogue.
// 93KB smem + 32K regs per CTA -> one STEP CTA and one INPUT CTA co-reside on
// each SM (16 warps, two independent instruction streams) under the R15
// fork/join two-stream schedule: input slice t (s2, low prio) -> event -> step t.

#define CTRL  1024
#define STAGE 30720                    // A1 5120 | A0 5120 | B1 10240 | B0 10240
#define NSTAGE 3
#define SMEM_BYTES (CTRL + NSTAGE * STAGE)  // 93184
#define QMAXF 32512.0f

// ------------------------- static device scratch -------------------------
__device__ float d_Xg[268435456];      // pre-gates (+bias), fragment order
__device__ float d_Cfrag[1048576];     // cell state, fragment order
__device__ __align__(256) signed char d_hq1[2][1048576];
__device__ __align__(256) signed char d_hq0[2][1048576];
__device__ __align__(256) signed char d_Wihq1[4194304];
__device__ __align__(256) signed char d_Wihq0[4194304];
__device__ __align__(256) signed char d_Whhq1[4194304];
__device__ __align__(256) signed char d_Whhq0[4194304];
__device__ __align__(256) signed char d_embq1[51200000];
__device__ __align__(256) signed char d_embq0[51200000];
__device__ unsigned d_absmax[4];       // 0=Wih 1=Whh 2=emb 3=h0
__device__ float d_logits[131072];     // [T][B][2]

// ------------------------- helpers -------------------------
__device__ __forceinline__ uint32_t smem_u32(const void* p) {
    uint32_t a;
    asm("{ .reg .u64 t; cvta.to.shared.u64 t, %1; cvt.u32.u64 %0, t; }" : "=r"(a) : "l"(p));
    return a;
}

#define CP16(dst, src) \
    asm volatile("cp.async.cg.shared.global [%0], [%1], 16;" :: "r"(dst), "l"(src) : "memory")
#define CP_COMMIT() asm volatile("cp.async.commit_group;" ::: "memory")
#define CP_WAIT1()  asm volatile("cp.async.wait_group 1;" ::: "memory")

#define LDSM4(r0, r1, r2, r3, addr) \
    asm volatile("ldmatrix.sync.aligned.m8n8.x4.shared.b16 {%0,%1,%2,%3}, [%4];" \
        : "=r"(r0), "=r"(r1), "=r"(r2), "=r"(r3) : "r"(addr))

__device__ __forceinline__ void mma_s8(int* d, const uint32_t* a, const uint32_t* b) {
    asm volatile(
        "mma.sync.aligned.m16n8k32.row.col.s32.s8.s8.s32 "
        "{%0,%1,%2,%3}, {%4,%5,%6,%7}, {%8,%9}, {%0,%1,%2,%3};\n"
        : "+r"(d[0]), "+r"(d[1]), "+r"(d[2]), "+r"(d[3])
        : "r"(a[0]), "r"(a[1]), "r"(a[2]), "r"(a[3]), "r"(b[0]), "r"(b[1]));
}

// CTA-local col cl in [0,128) -> global n: cl = wn*32 + nf*8 + f, nf = gate
__device__ __forceinline__ int n_of(int cl, int hc0) {
    int wn_ = cl >> 5;
    int nf  = (cl >> 3) & 3;
    int f   = cl & 7;
    return nf * 1024 + hc0 + wn_ * 8 + f;
}

__device__ __forceinline__ void quant16(float v, float inv_s, signed char* a1, signed char* a0) {
    int q = __float2int_rn(v * inv_s);
    q = max(-32512, min(32512, q));
    int q1 = (q + 128) >> 8;
    *a1 = (signed char)q1;
    *a0 = (signed char)(q - (q1 << 8));
}
__device__ __forceinline__ void quant16x4(float4 v, float inv_s, char4* o1, char4* o0) {
    char4 c1, c0;
    quant16(v.x, inv_s, &c1.x, &c0.x);
    quant16(v.y, inv_s, &c1.y, &c0.y);
    quant16(v.z, inv_s, &c1.z, &c0.z);
    quant16(v.w, inv_s, &c1.w, &c0.w);
    *o1 = c1; *o0 = c0;
}

// one K=64 chunk (2x k32), 3-term split, warp tile 32x32, dependency-spaced order
__device__ __forceinline__ void gemm_chunk_i8(
    int acc1[2][4][4], int acc2[2][4][4],
    uint32_t aH, uint32_t aL, uint32_t bH, uint32_t bL)
{
#pragma unroll
    for (int ks = 0; ks < 2; ks++) {
        uint32_t off = ks * 32;
        uint32_t a1[2][4], a0[2][4], b1[8], b0[8];
        LDSM4(a1[0][0], a1[0][1], a1[0][2], a1[0][3], aH + off);
        LDSM4(a1[1][0], a1[1][1], a1[1][2], a1[1][3], aH + 1280 + off);
        LDSM4(a0[0][0], a0[0][1], a0[0][2], a0[0][3], aL + off);
        LDSM4(a0[1][0], a0[1][1], a0[1][2], a0[1][3], aL + 1280 + off);
        LDSM4(b1[0], b1[1], b1[2], b1[3], bH + off);
        LDSM4(b1[4], b1[5], b1[6], b1[7], bH + 1280 + off);
        LDSM4(b0[0], b0[1], b0[2], b0[3], bL + off);
        LDSM4(b0[4], b0[5], b0[6], b0[7], bL + 1280 + off);
#pragma unroll
        for (int mf = 0; mf < 2; mf++)
#pragma unroll
            for (int nf = 0; nf < 4; nf++)
                mma_s8(acc1[mf][nf], a1[mf], b1 + nf * 2);
#pragma unroll
        for (int mf = 0; mf < 2; mf++)
#pragma unroll
            for (int nf = 0; nf < 4; nf++)
                mma_s8(acc2[mf][nf], a1[mf], b0 + nf * 2);
#pragma unroll
        for (int mf = 0; mf < 2; mf++)
#pragma unroll
            for (int nf = 0; nf < 4; nf++)
                mma_s8(acc2[mf][nf], a0[mf], b1 + nf * 2);
    }
}

// ------------------------- absmax pre-pass -------------------------
__global__ void zero_absmax() {
    if (threadIdx.x < 4) d_absmax[threadIdx.x] = 0u;
}

__device__ __forceinline__ float amax4(float4 v) {
    return fmaxf(fmaxf(fabsf(v.x), fabsf(v.y)), fmaxf(fabsf(v.z), fabsf(v.w)));
}

__global__ void absmax_kernel(const float* __restrict__ Wih, const float* __restrict__ Whh,
                              const float* __restrict__ emb, const float* __restrict__ h0)
{
    long g = blockIdx.x * 256 + threadIdx.x;
    const long stride = 262144;
    float m0 = 0.f, m1 = 0.f, m2 = 0.f, m3 = 0.f;
    for (long i = g; i < 1048576L; i += stride) {
        m0 = fmaxf(m0, amax4(*(const float4*)&Wih[i * 4]));
        m1 = fmaxf(m1, amax4(*(const float4*)&Whh[i * 4]));
    }
    for (long i = g; i < 12800000L; i += stride)
        m2 = fmaxf(m2, amax4(*(const float4*)&emb[i * 4]));
    m3 = amax4(*(const float4*)&h0[g * 4]);
#pragma unroll
    for (int off = 16; off > 0; off >>= 1) {
        m0 = fmaxf(m0, __shfl_xor_sync(0xffffffffu, m0, off));
        m1 = fmaxf(m1, __shfl_xor_sync(0xffffffffu, m1, off));
        m2 = fmaxf(m2, __shfl_xor_sync(0xffffffffu, m2, off));
        m3 = fmaxf(m3, __shfl_xor_sync(0xffffffffu, m3, off));
    }
    if ((threadIdx.x & 31) == 0) {
        atomicMax(&d_absmax[0], __float_as_uint(m0));
        atomicMax(&d_absmax[1], __float_as_uint(m1));
        atomicMax(&d_absmax[2], __float_as_uint(m2));
        atomicMax(&d_absmax[3], __float_as_uint(m3));
    }
}

// ------------------------- init: quantize weights/emb/h0, layout c0 -------------------------
__global__ void init_quant(const float* __restrict__ Wih, const float* __restrict__ Whh,
                           const float* __restrict__ emb,
                           const float* __restrict__ h0,  const float* __restrict__ c0)
{
    int idx = blockIdx.x * 256 + threadIdx.x;
    float iWih = QMAXF / fmaxf(__uint_as_float(d_absmax[0]), 1e-20f);
    float iWhh = QMAXF / fmaxf(__uint_as_float(d_absmax[1]), 1e-20f);
    float iEmb = QMAXF / fmaxf(__uint_as_float(d_absmax[2]), 1e-20f);
    float iH0  = QMAXF / fmaxf(__uint_as_float(d_absmax[3]), 1e-20f);

    if (idx < 1048576) {
        quant16x4(*(const float4*)&Wih[idx * 4], iWih,
                  (char4*)&d_Wihq1[idx * 4], (char4*)&d_Wihq0[idx * 4]);
        quant16x4(*(const float4*)&Whh[idx * 4], iWhh,
                  (char4*)&d_Whhq1[idx * 4], (char4*)&d_Whhq0[idx * 4]);
    }
    for (long i = idx; i < 12800000L; i += 4194304L)
        quant16x4(*(const float4*)&emb[i * 4], iEmb,
                  (char4*)&d_embq1[i * 4], (char4*)&d_embq0[i * 4]);
    if (idx < 262144)
        quant16x4(*(const float4*)&h0[idx * 4], iH0,
                  (char4*)&d_hq1[0][idx * 4], (char4*)&d_hq0[0][idx * 4]);
    if (idx < 1048576) {
        // c0 -> fragment layout (8-warp / 64-row-tile geometry)
        int b = idx >> 10, hc = idx & 1023;
        int bm = b >> 6, rb = b & 63;
        int wm = rb >> 5, mf = (rb >> 4) & 1, rr = (rb >> 3) & 1, g = rb & 7;
        int bn = hc >> 5, hcl = hc & 31;
        int wn = hcl >> 3, tg = (hcl & 7) >> 1, e = hcl & 1;
        int warp = wn * 2 + wm, lane = g * 4 + tg, q = rr * 2 + e;
        int ci = (((bm * 32 + bn) * 8 + warp) * 2 + mf) * 128 + lane * 4 + q;
        d_Cfrag[ci] = c0[idx];
    }
    if (idx < 131072) d_logits[idx] = 0.0f;
}

// ------------------------- input GEMM slice for one t -------------------------
__global__ void __launch_bounds__(256, 2) input_slice(int t,
                                                      const int* __restrict__ x,
                                                      const float* __restrict__ b_ih,
                                                      const float* __restrict__ b_hh)
{
    extern __shared__ char smem[];
    uint32_t sb = smem_u32(smem);
    int tid = threadIdx.x;
    int bn = blockIdx.x;
    int bm_g = t * 16 + blockIdx.y;      // global 64-row tile index (0..1023)
    int warp = tid >> 5, lane = tid & 31;
    int wm = warp & 1, wn = warp >> 1;
    int tg = lane & 3;
    int hc0 = bn * 32;

    float sAB = (__uint_as_float(d_absmax[2]) / QMAXF) * (__uint_as_float(d_absmax[0]) / QMAXF);
    float sHIc = sAB * 65536.0f, sLOc = sAB * 256.0f;

    int* toks = (int*)(smem + 512);
    if (tid < 64) {
        int row = bm_g * 64 + tid;       // row = t*B + b
        toks[tid] = x[(row & 1023) * 64 + (row >> 10)];
    }
    __syncthreads();

    int r = tid >> 2, c = tid & 3;       // r 0..63
    uint32_t offA  = (uint32_t)(r * 80 + c * 16);
    uint32_t offB1 = (uint32_t)((r + 64) * 80 + c * 16);
    size_t aoff  = (size_t)toks[r] * 1024 + c * 16;
    size_t boff0 = (size_t)n_of(r,      hc0) * 1024 + c * 16;
    size_t boff1 = (size_t)n_of(r + 64, hc0) * 1024 + c * 16;

    uint32_t laneA = (uint32_t)((wm * 32 + (lane & 15)) * 80 + (lane >> 4) * 16);
    uint32_t laneB = (uint32_t)((wn * 32 + ((lane >> 4) << 3) + (lane & 7)) * 80
                                + ((lane >> 3) & 1) * 16);

    int acc1[2][4][4], acc2[2][4][4];
#pragma unroll
    for (int i = 0; i < 2; i++)
#pragma unroll
        for (int j = 0; j < 4; j++)
#pragma unroll
            for (int q = 0; q < 4; q++) { acc1[i][j][q] = 0; acc2[i][j][q] = 0; }

#pragma unroll
    for (int p = 0; p < 2; p++) {
        uint32_t st = sb + CTRL + p * STAGE;
        int k0 = p * 64;
        CP16(st +         offA,  d_embq1 + aoff + k0);
        CP16(st +  5120 + offA,  d_embq0 + aoff + k0);
        CP16(st + 10240 + offA,  d_Wihq1 + boff0 + k0);
        CP16(st + 10240 + offB1, d_Wihq1 + boff1 + k0);
        CP16(st + 20480 + offA,  d_Wihq0 + boff0 + k0);
        CP16(st + 20480 + offB1, d_Wihq0 + boff1 + k0);
        CP_COMMIT();
    }

    for (int kt = 0; kt < 16; kt++) {
        CP_WAIT1();
        __syncthreads();
        uint32_t s0 = sb + CTRL + (kt % 3) * STAGE;
        gemm_chunk_i8(acc1, acc2, s0 + laneA, s0 + 5120 + laneA,
                                  s0 + 10240 + laneB, s0 + 20480 + laneB);
        if (kt + 2 < 16) {
            int k0 = (kt + 2) * 64;
            uint32_t st = sb + CTRL + ((kt + 2) % 3) * STAGE;
            CP16(st +         offA,  d_embq1 + aoff + k0);
            CP16(st +  5120 + offA,  d_embq0 + aoff + k0);
            CP16(st + 10240 + offA,  d_Wihq1 + boff0 + k0);
            CP16(st + 10240 + offB1, d_Wihq1 + boff1 + k0);
            CP16(st + 20480 + offA,  d_Wihq0 + boff0 + k0);
            CP16(st + 20480 + offB1, d_Wihq0 + boff1 + k0);
        }
        CP_COMMIT();
    }

#pragma unroll
    for (int mf = 0; mf < 2; mf++)
#pragma unroll
        for (int nf = 0; nf < 4; nf++) {
            int n0 = nf * 1024 + hc0 + wn * 8 + 2 * tg;
            float be0 = b_ih[n0] + b_hh[n0];
            float be1 = b_ih[n0 + 1] + b_hh[n0 + 1];
            size_t off = ((((size_t)bm_g * 32 + bn) * 8 + warp) * 8 + mf * 4 + nf) * 128 + lane * 4;
            float4 v;
            v.x = sHIc * (float)acc1[mf][nf][0] + sLOc * (float)acc2[mf][nf][0] + be0;
            v.y = sHIc * (float)acc1[mf][nf][1] + sLOc * (float)acc2[mf][nf][1] + be1;
            v.z = sHIc * (float)acc1[mf][nf][2] + sLOc * (float)acc2[mf][nf][2] + be0;
            v.w = sHIc * (float)acc1[mf][nf][3] + sLOc * (float)acc2[mf][nf][3] + be1;
            *(float4*)&d_Xg[off] = v;
        }
}

// ------------------------- one recurrent step (R10 body) -------------------------
__global__ void __launch_bounds__(256, 2) step_kernel(int t,
                                                      const float* __restrict__ Wout,
                                                      const float* __restrict__ b_out,
                                                      float* __restrict__ out)
{
    extern __shared__ char smem[];
    uint32_t sb = smem_u32(smem);
    int tid = threadIdx.x;
    int bn = blockIdx.x, bm = blockIdx.y;   // bn 0..31, bm 0..15
    int warp = tid >> 5, lane = tid & 31;
    int wm = warp & 1, wn = warp >> 1;
    int g = lane >> 2, tg = lane & 3;
    int m0 = bm * 64, hc0 = bn * 32;

    if (t > 0 && bn == 0 && bm == 0) {
        int tb = (t - 1) << 11;
        for (int i = tid; i < 1024; i += 256) {
            float l0 = d_logits[tb + i * 2 + 0] + b_out[0];
            float l1 = d_logits[tb + i * 2 + 1] + b_out[1];
            float mx = fmaxf(l0, l1);
            float lse = mx + logf(expf(l0 - mx) + expf(l1 - mx));
            out[tb + i * 2 + 0] = l0 - lse;
            out[tb + i * 2 + 1] = l1 - lse;
        }
    }

    float sh  = (t == 0) ? (__uint_as_float(d_absmax[3]) / QMAXF) : (1.0f / QMAXF);
    float sAB = sh * (__uint_as_float(d_absmax[1]) / QMAXF);
    float sHIc = sAB * 65536.0f, sLOc = sAB * 256.0f;

    const signed char* hQ1 = d_hq1[t & 1];
    const signed char* hQ0 = d_hq0[t & 1];
    signed char* nQ1 = d_hq1[(t + 1) & 1];
    signed char* nQ0 = d_hq0[(t + 1) & 1];

    float* ws = (float*)smem;   // 64 floats: [cls][hcL 0..31]
    if (tid < 64) ws[tid] = Wout[(tid >> 5) * 1024 + hc0 + (tid & 31)];
    __syncthreads();

    int r = tid >> 2, c = tid & 3;
    uint32_t offA  = (uint32_t)(r * 80 + c * 16);
    uint32_t offB1 = (uint32_t)((r + 64) * 80 + c * 16);
    size_t aoff  = (size_t)(m0 + r) * 1024 + c * 16;
    size_t boff0 = (size_t)n_of(r,      hc0) * 1024 + c * 16;
    size_t boff1 = (size_t)n_of(r + 64, hc0) * 1024 + c * 16;

    uint32_t laneA = (uint32_t)((wm * 32 + (lane & 15)) * 80 + (lane >> 4) * 16);
    uint32_t laneB = (uint32_t)((wn * 32 + ((lane >> 4) << 3) + (lane & 7)) * 80
                                + ((lane >> 3) & 1) * 16);

    int acc1[2][4][4], acc2[2][4][4];
#pragma unroll
    for (int i = 0; i < 2; i++)
#pragma unroll
        for (int j = 0; j < 4; j++)
#pragma unroll
            for (int q = 0; q < 4; q++) { acc1[i][j][q] = 0; acc2[i][j][q] = 0; }

#pragma unroll
    for (int p = 0; p < 2; p++) {
        uint32_t st = sb + CTRL + p * STAGE;
        int k0 = p * 64;
        CP16(st +         offA,  hQ1 + aoff + k0);
        CP16(st +  5120 + offA,  hQ0 + aoff + k0);
        CP16(st + 10240 + offA,  d_Whhq1 + boff0 + k0);
        CP16(st + 10240 + offB1, d_Whhq1 + boff1 + k0);
        CP16(st + 20480 + offA,  d_Whhq0 + boff0 + k0);
        CP16(st + 20480 + offB1, d_Whhq0 + boff1 + k0);
        CP_COMMIT();
    }

    for (int kt = 0; kt < 16; kt++) {
        CP_WAIT1();
        __syncthreads();
        uint32_t s0 = sb + CTRL + (kt % 3) * STAGE;
        gemm_chunk_i8(acc1, acc2, s0 + laneA, s0 + 5120 + laneA,
                                  s0 + 10240 + laneB, s0 + 20480 + laneB);
        if (kt + 2 < 16) {
            int k0 = (kt + 2) * 64;
            uint32_t st = sb + CTRL + ((kt + 2) % 3) * STAGE;
            CP16(st +         offA,  hQ1 + aoff + k0);
            CP16(st +  5120 + offA,  hQ0 + aoff + k0);
            CP16(st + 10240 + offA,  d_Whhq1 + boff0 + k0);
            CP16(st + 10240 + offB1, d_Whhq1 + boff1 + k0);
            CP16(st + 20480 + offA,  d_Whhq0 + boff0 + k0);
            CP16(st + 20480 + offB1, d_Whhq0 + boff1 + k0);
        }
        CP_COMMIT();
    }

    // ---------------- fused LSTM epilogue ----------------
    size_t xgbase = ((((size_t)(t * 16 + bm) * 32 + bn) * 8 + warp) * 8) * 128 + lane * 4;
    size_t cbase  = ((((size_t)bm * 32 + bn) * 8 + warp) * 2) * 128 + lane * 4;

    float lsum[2][2][2];
#pragma unroll
    for (int i = 0; i < 2; i++)
#pragma unroll
        for (int j = 0; j < 2; j++) { lsum[i][j][0] = 0.0f; lsum[i][j][1] = 0.0f; }

#pragma unroll
    for (int mf = 0; mf < 2; mf++) {
        float4 CPc = *(const float4*)&d_Cfrag[cbase + mf * 128];
        float cprev[4] = {CPc.x, CPc.y, CPc.z, CPc.w};
        float4 PI = *(const float4*)&d_Xg[xgbase + (size_t)(mf * 4 + 0) * 128];
        float4 PF = *(const float4*)&d_Xg[xgbase + (size_t)(mf * 4 + 1) * 128];
        float4 PG = *(const float4*)&d_Xg[xgbase + (size_t)(mf * 4 + 2) * 128];
        float4 PO = *(const float4*)&d_Xg[xgbase + (size_t)(mf * 4 + 3) * 128];
        float pri[4] = {PI.x, PI.y, PI.z, PI.w};
        float prf[4] = {PF.x, PF.y, PF.z, PF.w};
        float prg[4] = {PG.x, PG.y, PG.z, PG.w};
        float pro[4] = {PO.x, PO.y, PO.z, PO.w};
        float cnew[4];
#pragma unroll
        for (int q = 0; q < 4; q++) {
            int rr = q >> 1, e = q & 1;
            float I = sHIc * (float)acc1[mf][0][q] + sLOc * (float)acc2[mf][0][q] + pri[q];
            float F = sHIc * (float)acc1[mf][1][q] + sLOc * (float)acc2[mf][1][q] + prf[q];
            float G = sHIc * (float)acc1[mf][2][q] + sLOc * (float)acc2[mf][2][q] + prg[q];
            float O = sHIc * (float)acc1[mf][3][q] + sLOc * (float)acc2[mf][3][q] + pro[q];
            float si = 1.0f / (1.0f + expf(-I));
            float sf = 1.0f / (1.0f + expf(-F));
            float so = 1.0f / (1.0f + expf(-O));
            float c2 = sf * cprev[q] + si * tanhf(G);
            float h2 = so * tanhf(c2);
            cnew[q] = c2;
            int b  = m0 + wm * 32 + mf * 16 + rr * 8 + g;
            int hcL = wn * 8 + 2 * tg + e;
            int hc = hc0 + hcL;
            int qh = __float2int_rn(h2 * QMAXF);
            int qh1 = (qh + 128) >> 8;
            nQ1[b * 1024 + hc] = (signed char)qh1;
            nQ0[b * 1024 + hc] = (signed char)(qh - (qh1 << 8));
            lsum[mf][rr][0] += c2 * ws[hcL];
            lsum[mf][rr][1] += c2 * ws[32 + hcL];
        }
        *(float4*)&d_Cfrag[cbase + mf * 128] = make_float4(cnew[0], cnew[1], cnew[2], cnew[3]);
    }

#pragma unroll
    for (int mf = 0; mf < 2; mf++)
#pragma unroll
        for (int rr = 0; rr < 2; rr++)
#pragma unroll
            for (int cls = 0; cls < 2; cls++) {
                float v = lsum[mf][rr][cls];
                v += __shfl_xor_sync(0xffffffffu, v, 1);
                v += __shfl_xor_sync(0xffffffffu, v, 2);
                if (tg == 0) {
                    int b = m0 + wm * 32 + mf * 16 + rr * 8 + g;
                    atomicAdd(&d_logits[(t << 11) + b * 2 + cls], v);
                }
            }
}

// ------------------------- finalize t=63 + out_final -------------------------
__global__ void final_kernel(const float* __restrict__ b_out, float* __restrict__ out)
{
    int i = blockIdx.x * 256 + threadIdx.x;
    if (i < 1024) {
        int tb = 63 << 11;
        float l0 = d_logits[tb + i * 2 + 0] + b_out[0];
        float l1 = d_logits[tb + i * 2 + 1] + b_out[1];
        float mx = fmaxf(l0, l1);
        float lse = mx + logf(expf(l0 - mx) + expf(l1 - mx));
        out[tb + i * 2 + 0] = l0 - lse;
        out[tb + i * 2 + 1] = l1 - lse;
        out[131072 + i * 2 + 0] = l0;
        out[131072 + i * 2 + 1] = l1;
    }
}

// ------------------------- launch (fork/join over two streams) -------------------------
extern "C" void kernel_launch(void* const* d_in, const int* in_sizes, int n_in,
                              void* d_out, int out_size)
{
    (void)in_sizes; (void)n_in; (void)out_size;
    const int*   x    = (const int*)d_in[0];
    const float* emb  = (const float*)d_in[1];
    const float* Wih  = (const float*)d_in[2];
    const float* Whh  = (const float*)d_in[3];
    const float* bih  = (const float*)d_in[4];
    const float* bhh  = (const float*)d_in[5];
    const float* Wout = (const float*)d_in[6];
    const float* bout = (const float*)d_in[7];
    const float* h0   = (const float*)d_in[8];
    const float* c0   = (const float*)d_in[9];
    float* out = (float*)d_out;

    cudaFuncSetAttribute(input_slice, cudaFuncAttributeMaxDynamicSharedMemorySize, SMEM_BYTES);
    cudaFuncSetAttribute(step_kernel, cudaFuncAttributeMaxDynamicSharedMemorySize, SMEM_BYTES);

    // host-side objects: created at capture time only
    int prLow, prHigh;
    cudaDeviceGetStreamPriorityRange(&prLow, &prHigh);
    cudaStream_t s2;
    cudaStreamCreateWithPriority(&s2, cudaStreamNonBlocking, prLow);  // input = low priority
    cudaEvent_t evFork;
    cudaEventCreateWithFlags(&evFork, cudaEventDisableTiming);
    static cudaEvent_t evSlice[64];
    for (int t = 0; t < 64; t++)
        cudaEventCreateWithFlags(&evSlice[t], cudaEventDisableTiming);

    // init phase on main stream
    zero_absmax<<<1, 32>>>();
    absmax_kernel<<<1024, 256>>>(Wih, Whh, emb, h0);
    init_quant<<<16384, 256>>>(Wih, Whh, emb, h0, c0);

    // fork: s2 depends on init
    cudaEventRecord(evFork, 0);
    cudaStreamWaitEvent(s2, evFork, 0);

    // input slices on s2 (in t order), each records its completion event
    for (int t = 0; t < 64; t++) {
        input_slice<<<dim3(32, 16), 256, SMEM_BYTES, s2>>>(t, x, bih, bhh);
        cudaEventRecord(evSlice[t], s2);
    }

    // step chain on main stream; step t joins on slice t
    for (int t = 0; t < 64; t++) {
        cudaStreamWaitEvent(0, evSlice[t], 0);
        step_kernel<<<dim3(32, 16), 256, SMEM_BYTES>>>(t, Wout, bout, out);
    }
    final_kernel<<<4, 256>>>(bout, out);
}